// round 1
// baseline (speedup 1.0000x reference)
#include <cuda_runtime.h>
#include <math.h>

#define SEQ   2048
#define BATCH 2
#define DMODEL 1024
#define NH    16
#define HS    64
#define FF    4096
#define MTOT  (BATCH*SEQ)   /* 4096 rows */

// ---------------- scratch (static device globals; no allocation) ----------------
__device__ float g_q[MTOT*DMODEL];
__device__ float g_k[MTOT*DMODEL];
__device__ float g_v[MTOT*DMODEL];
__device__ float g_attn[MTOT*DMODEL];
__device__ float g_y[MTOT*DMODEL];
__device__ float g_x1[MTOT*DMODEL];
__device__ float g_h[MTOT*FF];
__device__ float g_y2[MTOT*DMODEL];

// ---------------- generic 128x128x16 SGEMM, 256 threads, 8x8 microtile ----------
// headmode: B element (k, n) lives at  B + (n/64)*(K*64) + k*64 + (n%64)
//           (i.e. per-head weight [H][K][64] read as one [K, H*64] matrix)
__global__ void __launch_bounds__(256, 2)
gemm128(const float* __restrict__ A, const float* __restrict__ B,
        const float* __restrict__ bias, float* __restrict__ C,
        int K, int lda, int ldb, int ldc, int relu, int headmode)
{
    __shared__ float Ast[16][132];
    __shared__ float Bs[16][132];
    const int tid = threadIdx.x;
    const int m0 = blockIdx.y * 128;
    const int n0 = blockIdx.x * 128;
    const int ty = tid >> 4, tx = tid & 15;

    float acc[8][8];
#pragma unroll
    for (int i = 0; i < 8; i++)
#pragma unroll
        for (int j = 0; j < 8; j++) acc[i][j] = 0.f;

    for (int k0 = 0; k0 < K; k0 += 16) {
        // A tile -> transposed SMEM
#pragma unroll
        for (int i = 0; i < 2; i++) {
            int lin = tid + i * 256;        // 0..511
            int row = lin >> 2;             // 0..127
            int kq  = lin & 3;              // 0..3 (float4 within 16-wide k)
            float4 a4 = *(const float4*)(A + (size_t)(m0 + row) * lda + k0 + kq * 4);
            Ast[kq * 4 + 0][row] = a4.x;
            Ast[kq * 4 + 1][row] = a4.y;
            Ast[kq * 4 + 2][row] = a4.z;
            Ast[kq * 4 + 3][row] = a4.w;
        }
        // B tile
#pragma unroll
        for (int i = 0; i < 2; i++) {
            int lin = tid + i * 256;
            int kk = lin >> 5;              // 0..15
            int cq = lin & 31;              // 0..31 -> col cq*4
            int ncol = n0 + cq * 4;
            const float* bp;
            if (headmode)
                bp = B + (size_t)(ncol >> 6) * ((size_t)K * 64)
                       + (size_t)(k0 + kk) * 64 + (ncol & 63);
            else
                bp = B + (size_t)(k0 + kk) * ldb + ncol;
            *(float4*)&Bs[kk][cq * 4] = *(const float4*)bp;
        }
        __syncthreads();

#pragma unroll
        for (int kk = 0; kk < 16; kk++) {
            float4 a0 = *(float4*)&Ast[kk][ty * 4];
            float4 a1 = *(float4*)&Ast[kk][64 + ty * 4];
            float4 b0 = *(float4*)&Bs[kk][tx * 4];
            float4 b1 = *(float4*)&Bs[kk][64 + tx * 4];
            float av[8] = {a0.x, a0.y, a0.z, a0.w, a1.x, a1.y, a1.z, a1.w};
            float bv[8] = {b0.x, b0.y, b0.z, b0.w, b1.x, b1.y, b1.z, b1.w};
#pragma unroll
            for (int i = 0; i < 8; i++)
#pragma unroll
                for (int j = 0; j < 8; j++)
                    acc[i][j] = fmaf(av[i], bv[j], acc[i][j]);
        }
        __syncthreads();
    }

    // epilogue
#pragma unroll
    for (int ih = 0; ih < 2; ih++)
#pragma unroll
        for (int i = 0; i < 4; i++) {
            int row = m0 + ih * 64 + ty * 4 + i;
#pragma unroll
            for (int jh = 0; jh < 2; jh++) {
                int col = n0 + jh * 64 + tx * 4;
                float4 r;
                r.x = acc[ih * 4 + i][jh * 4 + 0];
                r.y = acc[ih * 4 + i][jh * 4 + 1];
                r.z = acc[ih * 4 + i][jh * 4 + 2];
                r.w = acc[ih * 4 + i][jh * 4 + 3];
                if (bias) {
                    float4 bv4 = *(const float4*)(bias + col);
                    r.x += bv4.x; r.y += bv4.y; r.z += bv4.z; r.w += bv4.w;
                }
                if (relu) {
                    r.x = fmaxf(r.x, 0.f); r.y = fmaxf(r.y, 0.f);
                    r.z = fmaxf(r.z, 0.f); r.w = fmaxf(r.w, 0.f);
                }
                *(float4*)(C + (size_t)row * ldc + col) = r;
            }
        }
}

// ---------------- causal flash attention ----------------
// q,k,v in [B, S, H*64] layout; out in [B, S, H*64] (concat heads)
// block: 16 queries for one (b, h); 256 threads; key tiles of 64
__global__ void __launch_bounds__(256)
attn_kernel(const float* __restrict__ q, const float* __restrict__ k,
            const float* __restrict__ v, float* __restrict__ out)
{
    __shared__ float Qs[16][68];
    __shared__ float Ks[64][68];
    __shared__ float Vs[64][68];
    __shared__ float Ss[16][68];
    __shared__ float sm_m[16], sm_l[16], sm_scale[16];
    __shared__ float pmax[16][16], psum[16][16];

    const int tid = threadIdx.x;
    const int r  = tid >> 4;   // query row within tile (0..15)
    const int cg = tid & 15;   // column group (0..15)
    const int b = blockIdx.z;
    const int h = blockIdx.y;
    const int q0 = blockIdx.x * 16;
    const float SCALE = 0.125f;   // 1/sqrt(64)

    // load Q tile (one float4 per thread)
    {
        const float4 qv = *(const float4*)(q + (size_t)(b * SEQ + q0 + r) * DMODEL + h * HS + cg * 4);
        *(float4*)&Qs[r][cg * 4] = qv;
    }
    if (cg == 0) { sm_m[r] = -INFINITY; sm_l[r] = 0.f; }

    float o0 = 0.f, o1 = 0.f, o2 = 0.f, o3 = 0.f;
    const int ktiles = (q0 + 15) / 64 + 1;

    for (int kt = 0; kt < ktiles; kt++) {
        const int kt0 = kt * 64;
        __syncthreads();  // protect Ks/Vs from previous iteration (and Q/m/l init)

        // load K,V tiles: 64x64 each, 4 float4 per thread
#pragma unroll
        for (int j = 0; j < 4; j++) {
            int lin = tid + j * 256;   // float4 index 0..1023
            int c  = lin >> 4;         // key within tile 0..63
            int dq = lin & 15;
            size_t g = (size_t)(b * SEQ + kt0 + c) * DMODEL + h * HS + dq * 4;
            *(float4*)&Ks[c][dq * 4] = *(const float4*)(k + g);
            *(float4*)&Vs[c][dq * 4] = *(const float4*)(v + g);
        }
        __syncthreads();

        // scores: thread (r, cg) computes keys c = cg*4 .. cg*4+3
        float s[4] = {0.f, 0.f, 0.f, 0.f};
#pragma unroll
        for (int d4 = 0; d4 < 16; d4++) {
            float4 q4 = *(float4*)&Qs[r][d4 * 4];
#pragma unroll
            for (int j = 0; j < 4; j++) {
                float4 k4 = *(float4*)&Ks[cg * 4 + j][d4 * 4];
                s[j] += q4.x * k4.x + q4.y * k4.y + q4.z * k4.z + q4.w * k4.w;
            }
        }
        float lmax = -INFINITY;
#pragma unroll
        for (int j = 0; j < 4; j++) {
            int kg = kt0 + cg * 4 + j;
            if (kg > q0 + r) s[j] = -INFINITY;
            else             s[j] *= SCALE;
            lmax = fmaxf(lmax, s[j]);
        }
        pmax[r][cg] = lmax;
        __syncthreads();

        if (cg == 0) {
            float m = sm_m[r], tm = -INFINITY;
#pragma unroll
            for (int i = 0; i < 16; i++) tm = fmaxf(tm, pmax[r][i]);
            float mn = fmaxf(m, tm);
            sm_scale[r] = __expf(m - mn);
            sm_m[r] = mn;
        }
        __syncthreads();

        const float mn = sm_m[r];
        float ps = 0.f;
#pragma unroll
        for (int j = 0; j < 4; j++) {
            float p = __expf(s[j] - mn);   // exp(-inf - finite) = 0 for masked
            Ss[r][cg * 4 + j] = p;
            ps += p;
        }
        psum[r][cg] = ps;
        __syncthreads();

        if (cg == 0) {
            float t = 0.f;
#pragma unroll
            for (int i = 0; i < 16; i++) t += psum[r][i];
            sm_l[r] = sm_l[r] * sm_scale[r] + t;
        }

        // O update (reads Ss, Vs, sm_scale — all ready)
        const float sc = sm_scale[r];
        o0 *= sc; o1 *= sc; o2 *= sc; o3 *= sc;
#pragma unroll
        for (int c = 0; c < 64; c++) {
            float p = Ss[r][c];
            float4 v4 = *(float4*)&Vs[c][cg * 4];
            o0 = fmaf(p, v4.x, o0);
            o1 = fmaf(p, v4.y, o1);
            o2 = fmaf(p, v4.z, o2);
            o3 = fmaf(p, v4.w, o3);
        }
    }
    __syncthreads();
    const float invl = 1.f / sm_l[r];
    float4 res = make_float4(o0 * invl, o1 * invl, o2 * invl, o3 * invl);
    *(float4*)(out + (size_t)(b * SEQ + q0 + r) * DMODEL + h * HS + cg * 4) = res;
}

// ---------------- fused residual + layernorm (one row per block) ----------------
__global__ void __launch_bounds__(256)
add_ln(const float* __restrict__ x, const float* __restrict__ y,
       const float* __restrict__ g, const float* __restrict__ be,
       float* __restrict__ out)
{
    __shared__ float red[256];
    const int row = blockIdx.x, tid = threadIdx.x;
    const size_t base = (size_t)row * DMODEL;
    float4 xv = ((const float4*)(x + base))[tid];
    float4 yv = ((const float4*)(y + base))[tid];
    float v0 = xv.x + yv.x, v1 = xv.y + yv.y, v2 = xv.z + yv.z, v3 = xv.w + yv.w;

    red[tid] = v0 + v1 + v2 + v3;
    __syncthreads();
    for (int s = 128; s > 0; s >>= 1) {
        if (tid < s) red[tid] += red[tid + s];
        __syncthreads();
    }
    const float mu = red[0] * (1.f / DMODEL);
    __syncthreads();

    float d0 = v0 - mu, d1 = v1 - mu, d2 = v2 - mu, d3 = v3 - mu;
    red[tid] = d0 * d0 + d1 * d1 + d2 * d2 + d3 * d3;
    __syncthreads();
    for (int s = 128; s > 0; s >>= 1) {
        if (tid < s) red[tid] += red[tid + s];
        __syncthreads();
    }
    const float rstd = rsqrtf(red[0] * (1.f / DMODEL) + 1e-5f);

    float4 gv = ((const float4*)g)[tid];
    float4 bv = ((const float4*)be)[tid];
    float4 o;
    o.x = d0 * rstd * gv.x + bv.x;
    o.y = d1 * rstd * gv.y + bv.y;
    o.z = d2 * rstd * gv.z + bv.z;
    o.w = d3 * rstd * gv.w + bv.w;
    ((float4*)(out + base))[tid] = o;
}

// ---------------- host driver ----------------
extern "C" void kernel_launch(void* const* d_in, const int* in_sizes, int n_in,
                              void* d_out, int out_size)
{
    const float* x      = (const float*)d_in[0];
    const float* wq     = (const float*)d_in[1];
    const float* wk     = (const float*)d_in[2];
    const float* wv     = (const float*)d_in[3];
    const float* w_proj = (const float*)d_in[4];
    const float* b_proj = (const float*)d_in[5];
    const float* w1     = (const float*)d_in[6];
    const float* b1     = (const float*)d_in[7];
    const float* w2     = (const float*)d_in[8];
    const float* b2     = (const float*)d_in[9];
    const float* g1     = (const float*)d_in[10];
    const float* be1    = (const float*)d_in[11];
    const float* g2     = (const float*)d_in[12];
    const float* be2    = (const float*)d_in[13];
    float* out = (float*)d_out;

    float *q, *k, *v, *attn, *y, *x1, *hbuf, *y2;
    cudaGetSymbolAddress((void**)&q,    g_q);
    cudaGetSymbolAddress((void**)&k,    g_k);
    cudaGetSymbolAddress((void**)&v,    g_v);
    cudaGetSymbolAddress((void**)&attn, g_attn);
    cudaGetSymbolAddress((void**)&y,    g_y);
    cudaGetSymbolAddress((void**)&x1,   g_x1);
    cudaGetSymbolAddress((void**)&hbuf, g_h);
    cudaGetSymbolAddress((void**)&y2,   g_y2);

    dim3 blk(256);

    // QKV: fused over heads via headmode B indexing -> [B,S,H*64]
    dim3 gq(DMODEL / 128, MTOT / 128);           // (8, 32)
    gemm128<<<gq, blk>>>(x, wq, nullptr, q, DMODEL, DMODEL, 0, DMODEL, 0, 1);
    gemm128<<<gq, blk>>>(x, wk, nullptr, k, DMODEL, DMODEL, 0, DMODEL, 0, 1);
    gemm128<<<gq, blk>>>(x, wv, nullptr, v, DMODEL, DMODEL, 0, DMODEL, 0, 1);

    // causal attention -> [B,S,H*64] (concat heads)
    dim3 ga(SEQ / 16, NH, BATCH);                // (128, 16, 2)
    attn_kernel<<<ga, blk>>>(q, k, v, attn);

    // output projection
    gemm128<<<gq, blk>>>(attn, w_proj, b_proj, y, DMODEL, DMODEL, DMODEL, DMODEL, 0, 0);

    // x1 = LN(x + y)
    add_ln<<<MTOT, blk>>>(x, y, g1, be1, x1);

    // MLP
    dim3 gm1(FF / 128, MTOT / 128);              // (32, 32)
    gemm128<<<gm1, blk>>>(x1, w1, b1, hbuf, DMODEL, DMODEL, FF, FF, 1, 0);
    dim3 gm2(DMODEL / 128, MTOT / 128);          // (8, 32)
    gemm128<<<gm2, blk>>>(hbuf, w2, b2, y2, FF, FF, DMODEL, DMODEL, 0, 0);

    // out = LN(x1 + y2)
    add_ln<<<MTOT, blk>>>(x1, y2, g2, be2, out);
}

// round 2
// speedup vs baseline: 3.0300x; 3.0300x over previous
#include <cuda_runtime.h>
#include <math.h>

#define SEQ   2048
#define BATCH 2
#define DMODEL 1024
#define NH    16
#define HS    64
#define FF    4096
#define MTOT  (BATCH*SEQ)   /* 4096 rows */

// ---------------- scratch (static device globals; no allocation) ----------------
__device__ float g_q[MTOT*DMODEL];
__device__ float g_k[MTOT*DMODEL];
__device__ float g_v[MTOT*DMODEL];
__device__ float g_attn[MTOT*DMODEL];
__device__ float g_y[MTOT*DMODEL];
__device__ float g_x1[MTOT*DMODEL];
__device__ float g_h[MTOT*FF];
__device__ float g_y2[MTOT*DMODEL];

__device__ __forceinline__ float f2tf32(float x) {
    unsigned r;
    asm("cvt.rna.tf32.f32 %0, %1;" : "=r"(r) : "f"(x));
    return __uint_as_float(r);
}

// ---------------- tf32 tensor-core GEMM: 128x128 CTA tile, kchunk 32 ----------------
// 8 warps in 2(M)x4(N); each warp 64x32 via m16n8k8 mma.
// headmode: B element (k, n) lives at B + (n/64)*(K*64) + k*64 + (n%64)
__global__ void __launch_bounds__(256, 2)
gemm_tf32(const float* __restrict__ A, const float* __restrict__ B,
          const float* __restrict__ bias, float* __restrict__ C,
          int K, int lda, int ldb, int ldc, int relu, int headmode)
{
    __shared__ float As[128][36];   // padded: frag loads hit 32 distinct banks
    __shared__ float Bs[32][136];

    const int tid  = threadIdx.x;
    const int warp = tid >> 5, lane = tid & 31;
    const int wm = warp >> 2, wn = warp & 3;
    const int grp = lane >> 2, thr = lane & 3;
    const int m0 = blockIdx.y * 128;
    const int n0 = blockIdx.x * 128;

    float acc[4][4][4];
#pragma unroll
    for (int i = 0; i < 4; i++)
#pragma unroll
        for (int j = 0; j < 4; j++)
#pragma unroll
            for (int c = 0; c < 4; c++) acc[i][j][c] = 0.f;

    for (int k0 = 0; k0 < K; k0 += 32) {
        __syncthreads();
        // A chunk: 128x32 (1024 float4)
#pragma unroll
        for (int i = 0; i < 4; i++) {
            int idx = tid + i * 256;
            int row = idx >> 3, kq = idx & 7;
            float4 a = *(const float4*)(A + (size_t)(m0 + row) * lda + k0 + kq * 4);
            As[row][kq * 4 + 0] = f2tf32(a.x);
            As[row][kq * 4 + 1] = f2tf32(a.y);
            As[row][kq * 4 + 2] = f2tf32(a.z);
            As[row][kq * 4 + 3] = f2tf32(a.w);
        }
        // B chunk: 32x128
#pragma unroll
        for (int i = 0; i < 4; i++) {
            int idx = tid + i * 256;
            int row = idx >> 5, cq = idx & 31;
            int ncol = n0 + cq * 4;
            const float* bp;
            if (headmode)
                bp = B + (size_t)(ncol >> 6) * ((size_t)K * 64)
                       + (size_t)(k0 + row) * 64 + (ncol & 63);
            else
                bp = B + (size_t)(k0 + row) * ldb + ncol;
            float4 b = *(const float4*)bp;
            Bs[row][cq * 4 + 0] = f2tf32(b.x);
            Bs[row][cq * 4 + 1] = f2tf32(b.y);
            Bs[row][cq * 4 + 2] = f2tf32(b.z);
            Bs[row][cq * 4 + 3] = f2tf32(b.w);
        }
        __syncthreads();

#pragma unroll
        for (int ks = 0; ks < 4; ks++) {
            const int kk = ks * 8;
            unsigned a[4][4], b[4][2];
#pragma unroll
            for (int i = 0; i < 4; i++) {
                int rm = wm * 64 + i * 16 + grp;
                a[i][0] = __float_as_uint(As[rm    ][kk + thr    ]);
                a[i][1] = __float_as_uint(As[rm + 8][kk + thr    ]);
                a[i][2] = __float_as_uint(As[rm    ][kk + thr + 4]);
                a[i][3] = __float_as_uint(As[rm + 8][kk + thr + 4]);
            }
#pragma unroll
            for (int j = 0; j < 4; j++) {
                int cn = wn * 32 + j * 8 + grp;
                b[j][0] = __float_as_uint(Bs[kk + thr    ][cn]);
                b[j][1] = __float_as_uint(Bs[kk + thr + 4][cn]);
            }
#pragma unroll
            for (int i = 0; i < 4; i++)
#pragma unroll
                for (int j = 0; j < 4; j++)
                    asm volatile(
                        "mma.sync.aligned.m16n8k8.row.col.f32.tf32.tf32.f32 "
                        "{%0,%1,%2,%3},{%4,%5,%6,%7},{%8,%9},{%0,%1,%2,%3};"
                        : "+f"(acc[i][j][0]), "+f"(acc[i][j][1]),
                          "+f"(acc[i][j][2]), "+f"(acc[i][j][3])
                        : "r"(a[i][0]), "r"(a[i][1]), "r"(a[i][2]), "r"(a[i][3]),
                          "r"(b[j][0]), "r"(b[j][1]));
        }
    }

    // epilogue
#pragma unroll
    for (int i = 0; i < 4; i++) {
        int row = m0 + wm * 64 + i * 16 + grp;
#pragma unroll
        for (int j = 0; j < 4; j++) {
            int col = n0 + wn * 32 + j * 8 + thr * 2;
            float2 r0 = make_float2(acc[i][j][0], acc[i][j][1]);
            float2 r1 = make_float2(acc[i][j][2], acc[i][j][3]);
            if (bias) {
                float2 bv = *(const float2*)(bias + col);
                r0.x += bv.x; r0.y += bv.y;
                r1.x += bv.x; r1.y += bv.y;
            }
            if (relu) {
                r0.x = fmaxf(r0.x, 0.f); r0.y = fmaxf(r0.y, 0.f);
                r1.x = fmaxf(r1.x, 0.f); r1.y = fmaxf(r1.y, 0.f);
            }
            *(float2*)(C + (size_t)row * ldc + col) = r0;
            *(float2*)(C + (size_t)(row + 8) * ldc + col) = r1;
        }
    }
}

// ---------------- causal flash attention (fp32, swizzled, 2 rows/thread) ----------
// q,k,v in [B, S, H*64]; 32 queries per CTA; 256 threads; key tiles of 64.
__global__ void __launch_bounds__(256)
attn_kernel(const float* __restrict__ q, const float* __restrict__ k,
            const float* __restrict__ v, float* __restrict__ out)
{
    __shared__ float sm[12288];        // 48KB: Qs 2048 | Ks 4096 | Vs 4096 | Ss 2048
    float* Qs = sm;
    float* Ks = sm + 2048;
    float* Vs = sm + 6144;
    float* Ss = sm + 10240;

    const int tid = threadIdx.x;
    const int r  = tid >> 4;    // 0..15
    const int cg = tid & 15;    // 0..15
    const int b = blockIdx.z, h = blockIdx.y;
    const int q0 = blockIdx.x * 32;
    const int ra = r, rb = r + 16;
    const float SCALE = 0.125f;

    const int swa = (ra >> 2) & 7, swb = (rb >> 2) & 7, kswz = cg & 7;

    // load Q rows ra, rb (swizzled)
    {
        size_t ga = (size_t)(b * SEQ + q0 + ra) * DMODEL + h * HS + cg * 4;
        size_t gb = (size_t)(b * SEQ + q0 + rb) * DMODEL + h * HS + cg * 4;
        *(float4*)&Qs[ra * 64 + ((cg ^ swa) << 2)] = *(const float4*)(q + ga);
        *(float4*)&Qs[rb * 64 + ((cg ^ swb) << 2)] = *(const float4*)(q + gb);
    }

    float m_a = -INFINITY, m_b = -INFINITY, l_a = 0.f, l_b = 0.f;
    float oa0 = 0, oa1 = 0, oa2 = 0, oa3 = 0;
    float ob0 = 0, ob1 = 0, ob2 = 0, ob3 = 0;
    const int ktiles = q0 / 64 + 1;

    for (int kt = 0; kt < ktiles; kt++) {
        const int kt0 = kt * 64;
        __syncthreads();
        // load K,V tiles 64x64 (swizzled)
#pragma unroll
        for (int j = 0; j < 4; j++) {
            int lin = tid + j * 256;
            int c  = lin >> 4;
            int dq = lin & 15;
            size_t g = (size_t)(b * SEQ + kt0 + c) * DMODEL + h * HS + dq * 4;
            int ofs = c * 64 + ((dq ^ ((c >> 2) & 7)) << 2);
            *(float4*)&Ks[ofs] = *(const float4*)(k + g);
            *(float4*)&Vs[ofs] = *(const float4*)(v + g);
        }
        __syncthreads();

        // scores for keys 4cg..4cg+3 against both rows
        float sa[4] = {0, 0, 0, 0}, sb[4] = {0, 0, 0, 0};
#pragma unroll
        for (int d4 = 0; d4 < 16; d4++) {
            float4 qa = *(float4*)&Qs[ra * 64 + ((d4 ^ swa) << 2)];
            float4 qb = *(float4*)&Qs[rb * 64 + ((d4 ^ swb) << 2)];
#pragma unroll
            for (int j = 0; j < 4; j++) {
                float4 k4 = *(float4*)&Ks[(4 * cg + j) * 64 + ((d4 ^ kswz) << 2)];
                sa[j] += qa.x * k4.x + qa.y * k4.y + qa.z * k4.z + qa.w * k4.w;
                sb[j] += qb.x * k4.x + qb.y * k4.y + qb.z * k4.z + qb.w * k4.w;
            }
        }
        float la = -INFINITY, lb = -INFINITY;
#pragma unroll
        for (int j = 0; j < 4; j++) {
            int kg = kt0 + 4 * cg + j;
            sa[j] = (kg <= q0 + ra) ? sa[j] * SCALE : -INFINITY;
            sb[j] = (kg <= q0 + rb) ? sb[j] * SCALE : -INFINITY;
            la = fmaxf(la, sa[j]);
            lb = fmaxf(lb, sb[j]);
        }
#pragma unroll
        for (int o = 8; o; o >>= 1) {
            la = fmaxf(la, __shfl_xor_sync(0xffffffffu, la, o, 16));
            lb = fmaxf(lb, __shfl_xor_sync(0xffffffffu, lb, o, 16));
        }
        const float mna = fmaxf(m_a, la), mnb = fmaxf(m_b, lb);
        const float sca = __expf(m_a - mna), scb = __expf(m_b - mnb);
        m_a = mna; m_b = mnb;

        float psa = 0.f, psb = 0.f;
#pragma unroll
        for (int j = 0; j < 4; j++) {
            float pa = __expf(sa[j] - mna);
            float pb = __expf(sb[j] - mnb);
            Ss[ra * 64 + 4 * cg + j] = pa;
            Ss[rb * 64 + 4 * cg + j] = pb;
            psa += pa; psb += pb;
        }
#pragma unroll
        for (int o = 8; o; o >>= 1) {
            psa += __shfl_xor_sync(0xffffffffu, psa, o, 16);
            psb += __shfl_xor_sync(0xffffffffu, psb, o, 16);
        }
        l_a = l_a * sca + psa;
        l_b = l_b * scb + psb;
        __syncthreads();   // Ss visible to all

        oa0 *= sca; oa1 *= sca; oa2 *= sca; oa3 *= sca;
        ob0 *= scb; ob1 *= scb; ob2 *= scb; ob3 *= scb;
#pragma unroll
        for (int c = 0; c < 64; c++) {
            float pa = Ss[ra * 64 + c];
            float pb = Ss[rb * 64 + c];
            float4 v4 = *(float4*)&Vs[c * 64 + ((cg ^ ((c >> 2) & 7)) << 2)];
            oa0 = fmaf(pa, v4.x, oa0); oa1 = fmaf(pa, v4.y, oa1);
            oa2 = fmaf(pa, v4.z, oa2); oa3 = fmaf(pa, v4.w, oa3);
            ob0 = fmaf(pb, v4.x, ob0); ob1 = fmaf(pb, v4.y, ob1);
            ob2 = fmaf(pb, v4.z, ob2); ob3 = fmaf(pb, v4.w, ob3);
        }
    }

    const float ia = 1.f / l_a, ib = 1.f / l_b;
    size_t ga = (size_t)(b * SEQ + q0 + ra) * DMODEL + h * HS + cg * 4;
    size_t gb = (size_t)(b * SEQ + q0 + rb) * DMODEL + h * HS + cg * 4;
    *(float4*)(out + ga) = make_float4(oa0 * ia, oa1 * ia, oa2 * ia, oa3 * ia);
    *(float4*)(out + gb) = make_float4(ob0 * ib, ob1 * ib, ob2 * ib, ob3 * ib);
}

// ---------------- fused residual + layernorm (one row per block) ----------------
__global__ void __launch_bounds__(256)
add_ln(const float* __restrict__ x, const float* __restrict__ y,
       const float* __restrict__ g, const float* __restrict__ be,
       float* __restrict__ out)
{
    __shared__ float red[256];
    const int row = blockIdx.x, tid = threadIdx.x;
    const size_t base = (size_t)row * DMODEL;
    float4 xv = ((const float4*)(x + base))[tid];
    float4 yv = ((const float4*)(y + base))[tid];
    float v0 = xv.x + yv.x, v1 = xv.y + yv.y, v2 = xv.z + yv.z, v3 = xv.w + yv.w;

    red[tid] = v0 + v1 + v2 + v3;
    __syncthreads();
    for (int s = 128; s > 0; s >>= 1) {
        if (tid < s) red[tid] += red[tid + s];
        __syncthreads();
    }
    const float mu = red[0] * (1.f / DMODEL);
    __syncthreads();

    float d0 = v0 - mu, d1 = v1 - mu, d2 = v2 - mu, d3 = v3 - mu;
    red[tid] = d0 * d0 + d1 * d1 + d2 * d2 + d3 * d3;
    __syncthreads();
    for (int s = 128; s > 0; s >>= 1) {
        if (tid < s) red[tid] += red[tid + s];
        __syncthreads();
    }
    const float rstd = rsqrtf(red[0] * (1.f / DMODEL) + 1e-5f);

    float4 gv = ((const float4*)g)[tid];
    float4 bv = ((const float4*)be)[tid];
    float4 o;
    o.x = d0 * rstd * gv.x + bv.x;
    o.y = d1 * rstd * gv.y + bv.y;
    o.z = d2 * rstd * gv.z + bv.z;
    o.w = d3 * rstd * gv.w + bv.w;
    ((float4*)(out + base))[tid] = o;
}

// ---------------- host driver ----------------
extern "C" void kernel_launch(void* const* d_in, const int* in_sizes, int n_in,
                              void* d_out, int out_size)
{
    const float* x      = (const float*)d_in[0];
    const float* wq     = (const float*)d_in[1];
    const float* wk     = (const float*)d_in[2];
    const float* wv     = (const float*)d_in[3];
    const float* w_proj = (const float*)d_in[4];
    const float* b_proj = (const float*)d_in[5];
    const float* w1     = (const float*)d_in[6];
    const float* b1     = (const float*)d_in[7];
    const float* w2     = (const float*)d_in[8];
    const float* b2     = (const float*)d_in[9];
    const float* g1     = (const float*)d_in[10];
    const float* be1    = (const float*)d_in[11];
    const float* g2     = (const float*)d_in[12];
    const float* be2    = (const float*)d_in[13];
    float* out = (float*)d_out;

    float *q, *k, *v, *attn, *y, *x1, *hbuf, *y2;
    cudaGetSymbolAddress((void**)&q,    g_q);
    cudaGetSymbolAddress((void**)&k,    g_k);
    cudaGetSymbolAddress((void**)&v,    g_v);
    cudaGetSymbolAddress((void**)&attn, g_attn);
    cudaGetSymbolAddress((void**)&y,    g_y);
    cudaGetSymbolAddress((void**)&x1,   g_x1);
    cudaGetSymbolAddress((void**)&hbuf, g_h);
    cudaGetSymbolAddress((void**)&y2,   g_y2);

    dim3 blk(256);

    // QKV (headmode B indexing) -> [B,S,H*64]
    dim3 gq(DMODEL / 128, MTOT / 128);           // (8, 32)
    gemm_tf32<<<gq, blk>>>(x, wq, nullptr, q, DMODEL, DMODEL, 0, DMODEL, 0, 1);
    gemm_tf32<<<gq, blk>>>(x, wk, nullptr, k, DMODEL, DMODEL, 0, DMODEL, 0, 1);
    gemm_tf32<<<gq, blk>>>(x, wv, nullptr, v, DMODEL, DMODEL, 0, DMODEL, 0, 1);

    // causal attention -> [B,S,H*64]
    dim3 ga(SEQ / 32, NH, BATCH);                // (64, 16, 2)
    attn_kernel<<<ga, blk>>>(q, k, v, attn);

    // output projection
    gemm_tf32<<<gq, blk>>>(attn, w_proj, b_proj, y, DMODEL, DMODEL, DMODEL, DMODEL, 0, 0);

    // x1 = LN(x + y)
    add_ln<<<MTOT, blk>>>(x, y, g1, be1, x1);

    // MLP
    dim3 gm1(FF / 128, MTOT / 128);              // (32, 32)
    gemm_tf32<<<gm1, blk>>>(x1, w1, b1, hbuf, DMODEL, DMODEL, FF, FF, 1, 0);
    dim3 gm2(DMODEL / 128, MTOT / 128);          // (8, 32)
    gemm_tf32<<<gm2, blk>>>(hbuf, w2, b2, y2, FF, FF, DMODEL, DMODEL, 0, 0);

    // out = LN(x1 + y2)
    add_ln<<<MTOT, blk>>>(x1, y2, g2, be2, out);
}

// round 3
// speedup vs baseline: 4.7304x; 1.5612x over previous
#include <cuda_runtime.h>
#include <math.h>

#define SEQ   2048
#define BATCH 2
#define DMODEL 1024
#define NH    16
#define HS    64
#define FF    4096
#define MTOT  (BATCH*SEQ)   /* 4096 rows */

// ---------------- scratch (static device globals; no allocation) ----------------
__device__ float g_q[MTOT*DMODEL];
__device__ float g_k[MTOT*DMODEL];
__device__ float g_v[MTOT*DMODEL];
__device__ float g_attn[MTOT*DMODEL];
__device__ float g_y[MTOT*DMODEL];
__device__ float g_x1[MTOT*DMODEL];
__device__ float g_h[MTOT*FF];
__device__ float g_y2[MTOT*DMODEL];

__device__ __forceinline__ float f2tf32(float x) {
    unsigned r;
    asm("cvt.rna.tf32.f32 %0, %1;" : "=r"(r) : "f"(x));
    return __uint_as_float(r);
}

__device__ __forceinline__ void mma_tf32(float* c, const unsigned* a, const unsigned* b) {
    asm volatile(
        "mma.sync.aligned.m16n8k8.row.col.f32.tf32.tf32.f32 "
        "{%0,%1,%2,%3},{%4,%5,%6,%7},{%8,%9},{%0,%1,%2,%3};"
        : "+f"(c[0]), "+f"(c[1]), "+f"(c[2]), "+f"(c[3])
        : "r"(a[0]), "r"(a[1]), "r"(a[2]), "r"(a[3]),
          "r"(b[0]), "r"(b[1]));
}

// ---------------- tf32 tensor-core GEMM: 128x128 CTA tile, kchunk 32 ----------------
// 8 warps in 2(M)x4(N); each warp 64x32 via m16n8k8 mma.
// headmode: B element (k, n) lives at B + (n/64)*(K*64) + k*64 + (n%64)
__global__ void __launch_bounds__(256, 2)
gemm_tf32(const float* __restrict__ A, const float* __restrict__ B,
          const float* __restrict__ bias, float* __restrict__ C,
          int K, int lda, int ldb, int ldc, int relu, int headmode)
{
    __shared__ float As[128][36];
    __shared__ float Bs[32][136];

    const int tid  = threadIdx.x;
    const int warp = tid >> 5, lane = tid & 31;
    const int wm = warp >> 2, wn = warp & 3;
    const int grp = lane >> 2, thr = lane & 3;
    const int m0 = blockIdx.y * 128;
    const int n0 = blockIdx.x * 128;

    float acc[4][4][4];
#pragma unroll
    for (int i = 0; i < 4; i++)
#pragma unroll
        for (int j = 0; j < 4; j++)
#pragma unroll
            for (int c = 0; c < 4; c++) acc[i][j][c] = 0.f;

    for (int k0 = 0; k0 < K; k0 += 32) {
        __syncthreads();
#pragma unroll
        for (int i = 0; i < 4; i++) {
            int idx = tid + i * 256;
            int row = idx >> 3, kq = idx & 7;
            float4 a = *(const float4*)(A + (size_t)(m0 + row) * lda + k0 + kq * 4);
            As[row][kq * 4 + 0] = f2tf32(a.x);
            As[row][kq * 4 + 1] = f2tf32(a.y);
            As[row][kq * 4 + 2] = f2tf32(a.z);
            As[row][kq * 4 + 3] = f2tf32(a.w);
        }
#pragma unroll
        for (int i = 0; i < 4; i++) {
            int idx = tid + i * 256;
            int row = idx >> 5, cq = idx & 31;
            int ncol = n0 + cq * 4;
            const float* bp;
            if (headmode)
                bp = B + (size_t)(ncol >> 6) * ((size_t)K * 64)
                       + (size_t)(k0 + row) * 64 + (ncol & 63);
            else
                bp = B + (size_t)(k0 + row) * ldb + ncol;
            float4 b = *(const float4*)bp;
            Bs[row][cq * 4 + 0] = f2tf32(b.x);
            Bs[row][cq * 4 + 1] = f2tf32(b.y);
            Bs[row][cq * 4 + 2] = f2tf32(b.z);
            Bs[row][cq * 4 + 3] = f2tf32(b.w);
        }
        __syncthreads();

#pragma unroll
        for (int ks = 0; ks < 4; ks++) {
            const int kk = ks * 8;
            unsigned a[4][4], b[4][2];
#pragma unroll
            for (int i = 0; i < 4; i++) {
                int rm = wm * 64 + i * 16 + grp;
                a[i][0] = __float_as_uint(As[rm    ][kk + thr    ]);
                a[i][1] = __float_as_uint(As[rm + 8][kk + thr    ]);
                a[i][2] = __float_as_uint(As[rm    ][kk + thr + 4]);
                a[i][3] = __float_as_uint(As[rm + 8][kk + thr + 4]);
            }
#pragma unroll
            for (int j = 0; j < 4; j++) {
                int cn = wn * 32 + j * 8 + grp;
                b[j][0] = __float_as_uint(Bs[kk + thr    ][cn]);
                b[j][1] = __float_as_uint(Bs[kk + thr + 4][cn]);
            }
#pragma unroll
            for (int i = 0; i < 4; i++)
#pragma unroll
                for (int j = 0; j < 4; j++)
                    mma_tf32(acc[i][j], a[i], b[j]);
        }
    }

#pragma unroll
    for (int i = 0; i < 4; i++) {
        int row = m0 + wm * 64 + i * 16 + grp;
#pragma unroll
        for (int j = 0; j < 4; j++) {
            int col = n0 + wn * 32 + j * 8 + thr * 2;
            float2 r0 = make_float2(acc[i][j][0], acc[i][j][1]);
            float2 r1 = make_float2(acc[i][j][2], acc[i][j][3]);
            if (bias) {
                float2 bv = *(const float2*)(bias + col);
                r0.x += bv.x; r0.y += bv.y;
                r1.x += bv.x; r1.y += bv.y;
            }
            if (relu) {
                r0.x = fmaxf(r0.x, 0.f); r0.y = fmaxf(r0.y, 0.f);
                r1.x = fmaxf(r1.x, 0.f); r1.y = fmaxf(r1.y, 0.f);
            }
            *(float2*)(C + (size_t)row * ldc + col) = r0;
            *(float2*)(C + (size_t)(row + 8) * ldc + col) = r1;
        }
    }
}

// ---------------- causal flash attention on tensor cores (tf32 mma) -------------
// q,k,v in [B,S,H*64]; 64 queries/CTA, 4 warps (16 rows each), 64-key tiles.
// smem: Ks [64][68] | Vs [64][72] | Ps [64][68] (also Q staging) = 53248 B dynamic
#define ATT_SMEM_BYTES ((64*68 + 64*72 + 64*68) * 4)

__global__ void __launch_bounds__(128)
attn_kernel(const float* __restrict__ q, const float* __restrict__ k,
            const float* __restrict__ v, float* __restrict__ out)
{
    extern __shared__ float dsm[];
    float* Ks = dsm;                     // stride 68 (bank offset 4)
    float* Vs = dsm + 64 * 68;           // stride 72 (bank offset 8)
    float* Ps = dsm + 64 * 68 + 64 * 72; // stride 68; Q staging + P tile

    const int tid  = threadIdx.x;
    const int warp = tid >> 5, lane = tid & 31;
    const int grp = lane >> 2, thr = lane & 3;
    const int b = blockIdx.z, h = blockIdx.y;
    const int q0 = blockIdx.x * 64;
    const float SCALE = 0.125f;

    // ---- stage Q tile into Ps (tf32), coalesced ----
#pragma unroll
    for (int j = 0; j < 8; j++) {
        int lin = tid + j * 128;
        int row = lin >> 4, dq = lin & 15;
        float4 a = *(const float4*)(q + (size_t)(b * SEQ + q0 + row) * DMODEL + h * HS + dq * 4);
        Ps[row * 68 + dq * 4 + 0] = f2tf32(a.x);
        Ps[row * 68 + dq * 4 + 1] = f2tf32(a.y);
        Ps[row * 68 + dq * 4 + 2] = f2tf32(a.z);
        Ps[row * 68 + dq * 4 + 3] = f2tf32(a.w);
    }
    __syncthreads();

    // ---- Q A-fragments -> registers (reused every key tile) ----
    const int rA = warp * 16 + grp;       // local query row
    unsigned qf[8][4];
#pragma unroll
    for (int ks = 0; ks < 8; ks++) {
        qf[ks][0] = __float_as_uint(Ps[rA * 68 + ks * 8 + thr]);
        qf[ks][1] = __float_as_uint(Ps[(rA + 8) * 68 + ks * 8 + thr]);
        qf[ks][2] = __float_as_uint(Ps[rA * 68 + ks * 8 + thr + 4]);
        qf[ks][3] = __float_as_uint(Ps[(rA + 8) * 68 + ks * 8 + thr + 4]);
    }

    float o[8][4];
#pragma unroll
    for (int j = 0; j < 8; j++)
#pragma unroll
        for (int c = 0; c < 4; c++) o[j][c] = 0.f;
    float m0 = -INFINITY, m1 = -INFINITY, l0 = 0.f, l1 = 0.f;
    const int r0g = q0 + rA, r1g = r0g + 8;   // global query rows
    const int nt = q0 / 64 + 1;

    for (int kt = 0; kt < nt; kt++) {
        const int kt0 = kt * 64;
        __syncthreads();   // Ks/Vs reuse + Ps(Q) fragment reads done
        // ---- load K,V tiles (tf32) ----
#pragma unroll
        for (int j = 0; j < 8; j++) {
            int lin = tid + j * 128;
            int key = lin >> 4, dq = lin & 15;
            size_t g = (size_t)(b * SEQ + kt0 + key) * DMODEL + h * HS + dq * 4;
            float4 kv = *(const float4*)(k + g);
            float4 vv = *(const float4*)(v + g);
            Ks[key * 68 + dq * 4 + 0] = f2tf32(kv.x);
            Ks[key * 68 + dq * 4 + 1] = f2tf32(kv.y);
            Ks[key * 68 + dq * 4 + 2] = f2tf32(kv.z);
            Ks[key * 68 + dq * 4 + 3] = f2tf32(kv.w);
            Vs[key * 72 + dq * 4 + 0] = f2tf32(vv.x);
            Vs[key * 72 + dq * 4 + 1] = f2tf32(vv.y);
            Vs[key * 72 + dq * 4 + 2] = f2tf32(vv.z);
            Vs[key * 72 + dq * 4 + 3] = f2tf32(vv.w);
        }
        __syncthreads();

        // ---- S = Q K^T : 8 key n-blocks x 8 dim k-blocks ----
        float s[8][4];
#pragma unroll
        for (int j = 0; j < 8; j++) { s[j][0] = s[j][1] = s[j][2] = s[j][3] = 0.f; }
#pragma unroll
        for (int j = 0; j < 8; j++) {
#pragma unroll
            for (int ks = 0; ks < 8; ks++) {
                unsigned bf[2];
                bf[0] = __float_as_uint(Ks[(j * 8 + grp) * 68 + ks * 8 + thr]);
                bf[1] = __float_as_uint(Ks[(j * 8 + grp) * 68 + ks * 8 + thr + 4]);
                mma_tf32(s[j], qf[ks], bf);
            }
        }

        // ---- scale + causal mask (diagonal tile only) ----
        if (kt == nt - 1) {
#pragma unroll
            for (int j = 0; j < 8; j++) {
                int c0 = kt0 + j * 8 + 2 * thr;
                s[j][0] = (c0     <= r0g) ? s[j][0] * SCALE : -INFINITY;
                s[j][1] = (c0 + 1 <= r0g) ? s[j][1] * SCALE : -INFINITY;
                s[j][2] = (c0     <= r1g) ? s[j][2] * SCALE : -INFINITY;
                s[j][3] = (c0 + 1 <= r1g) ? s[j][3] * SCALE : -INFINITY;
            }
        } else {
#pragma unroll
            for (int j = 0; j < 8; j++) {
                s[j][0] *= SCALE; s[j][1] *= SCALE;
                s[j][2] *= SCALE; s[j][3] *= SCALE;
            }
        }

        // ---- online softmax (register + quad shuffles) ----
        float mx0 = -INFINITY, mx1 = -INFINITY;
#pragma unroll
        for (int j = 0; j < 8; j++) {
            mx0 = fmaxf(mx0, fmaxf(s[j][0], s[j][1]));
            mx1 = fmaxf(mx1, fmaxf(s[j][2], s[j][3]));
        }
        mx0 = fmaxf(mx0, __shfl_xor_sync(0xffffffffu, mx0, 1));
        mx0 = fmaxf(mx0, __shfl_xor_sync(0xffffffffu, mx0, 2));
        mx1 = fmaxf(mx1, __shfl_xor_sync(0xffffffffu, mx1, 1));
        mx1 = fmaxf(mx1, __shfl_xor_sync(0xffffffffu, mx1, 2));
        const float mn0 = fmaxf(m0, mx0), mn1 = fmaxf(m1, mx1);
        const float a0 = __expf(m0 - mn0), a1 = __expf(m1 - mn1);
        m0 = mn0; m1 = mn1;

        float ps0 = 0.f, ps1 = 0.f;
#pragma unroll
        for (int j = 0; j < 8; j++) {
            float p00 = __expf(s[j][0] - mn0);
            float p01 = __expf(s[j][1] - mn0);
            float p10 = __expf(s[j][2] - mn1);
            float p11 = __expf(s[j][3] - mn1);
            ps0 += p00 + p01; ps1 += p10 + p11;
            Ps[rA * 68 + j * 8 + 2 * thr]           = f2tf32(p00);
            Ps[rA * 68 + j * 8 + 2 * thr + 1]       = f2tf32(p01);
            Ps[(rA + 8) * 68 + j * 8 + 2 * thr]     = f2tf32(p10);
            Ps[(rA + 8) * 68 + j * 8 + 2 * thr + 1] = f2tf32(p11);
        }
        ps0 += __shfl_xor_sync(0xffffffffu, ps0, 1);
        ps0 += __shfl_xor_sync(0xffffffffu, ps0, 2);
        ps1 += __shfl_xor_sync(0xffffffffu, ps1, 1);
        ps1 += __shfl_xor_sync(0xffffffffu, ps1, 2);
        l0 = l0 * a0 + ps0;
        l1 = l1 * a1 + ps1;

#pragma unroll
        for (int j = 0; j < 8; j++) {
            o[j][0] *= a0; o[j][1] *= a0;
            o[j][2] *= a1; o[j][3] *= a1;
        }
        __syncwarp();   // P tile visible across lanes of this warp

        // ---- O += P V ----
#pragma unroll
        for (int ks = 0; ks < 8; ks++) {
            unsigned pa[4];
            pa[0] = __float_as_uint(Ps[rA * 68 + ks * 8 + thr]);
            pa[1] = __float_as_uint(Ps[(rA + 8) * 68 + ks * 8 + thr]);
            pa[2] = __float_as_uint(Ps[rA * 68 + ks * 8 + thr + 4]);
            pa[3] = __float_as_uint(Ps[(rA + 8) * 68 + ks * 8 + thr + 4]);
#pragma unroll
            for (int j = 0; j < 8; j++) {
                unsigned vb[2];
                vb[0] = __float_as_uint(Vs[(ks * 8 + thr) * 72 + j * 8 + grp]);
                vb[1] = __float_as_uint(Vs[(ks * 8 + thr + 4) * 72 + j * 8 + grp]);
                mma_tf32(o[j], pa, vb);
            }
        }
    }

    // ---- epilogue ----
    const float i0 = 1.f / l0, i1 = 1.f / l1;
    size_t base0 = (size_t)(b * SEQ + r0g) * DMODEL + h * HS;
    size_t base1 = (size_t)(b * SEQ + r1g) * DMODEL + h * HS;
#pragma unroll
    for (int j = 0; j < 8; j++) {
        int col = j * 8 + 2 * thr;
        *(float2*)(out + base0 + col) = make_float2(o[j][0] * i0, o[j][1] * i0);
        *(float2*)(out + base1 + col) = make_float2(o[j][2] * i1, o[j][3] * i1);
    }
}

// ---------------- fused residual + layernorm (one row per block) ----------------
__global__ void __launch_bounds__(256)
add_ln(const float* __restrict__ x, const float* __restrict__ y,
       const float* __restrict__ g, const float* __restrict__ be,
       float* __restrict__ out)
{
    __shared__ float red[256];
    const int row = blockIdx.x, tid = threadIdx.x;
    const size_t base = (size_t)row * DMODEL;
    float4 xv = ((const float4*)(x + base))[tid];
    float4 yv = ((const float4*)(y + base))[tid];
    float v0 = xv.x + yv.x, v1 = xv.y + yv.y, v2 = xv.z + yv.z, v3 = xv.w + yv.w;

    red[tid] = v0 + v1 + v2 + v3;
    __syncthreads();
    for (int s = 128; s > 0; s >>= 1) {
        if (tid < s) red[tid] += red[tid + s];
        __syncthreads();
    }
    const float mu = red[0] * (1.f / DMODEL);
    __syncthreads();

    float d0 = v0 - mu, d1 = v1 - mu, d2 = v2 - mu, d3 = v3 - mu;
    red[tid] = d0 * d0 + d1 * d1 + d2 * d2 + d3 * d3;
    __syncthreads();
    for (int s = 128; s > 0; s >>= 1) {
        if (tid < s) red[tid] += red[tid + s];
        __syncthreads();
    }
    const float rstd = rsqrtf(red[0] * (1.f / DMODEL) + 1e-5f);

    float4 gv = ((const float4*)g)[tid];
    float4 bv = ((const float4*)be)[tid];
    float4 oo;
    oo.x = d0 * rstd * gv.x + bv.x;
    oo.y = d1 * rstd * gv.y + bv.y;
    oo.z = d2 * rstd * gv.z + bv.z;
    oo.w = d3 * rstd * gv.w + bv.w;
    ((float4*)(out + base))[tid] = oo;
}

// ---------------- host driver ----------------
extern "C" void kernel_launch(void* const* d_in, const int* in_sizes, int n_in,
                              void* d_out, int out_size)
{
    const float* x      = (const float*)d_in[0];
    const float* wq     = (const float*)d_in[1];
    const float* wk     = (const float*)d_in[2];
    const float* wv     = (const float*)d_in[3];
    const float* w_proj = (const float*)d_in[4];
    const float* b_proj = (const float*)d_in[5];
    const float* w1     = (const float*)d_in[6];
    const float* b1     = (const float*)d_in[7];
    const float* w2     = (const float*)d_in[8];
    const float* b2     = (const float*)d_in[9];
    const float* g1     = (const float*)d_in[10];
    const float* be1    = (const float*)d_in[11];
    const float* g2     = (const float*)d_in[12];
    const float* be2    = (const float*)d_in[13];
    float* out = (float*)d_out;

    float *q, *k, *v, *attn, *y, *x1, *hbuf, *y2;
    cudaGetSymbolAddress((void**)&q,    g_q);
    cudaGetSymbolAddress((void**)&k,    g_k);
    cudaGetSymbolAddress((void**)&v,    g_v);
    cudaGetSymbolAddress((void**)&attn, g_attn);
    cudaGetSymbolAddress((void**)&y,    g_y);
    cudaGetSymbolAddress((void**)&x1,   g_x1);
    cudaGetSymbolAddress((void**)&hbuf, g_h);
    cudaGetSymbolAddress((void**)&y2,   g_y2);

    static int attn_smem_set = 0;
    if (!attn_smem_set) {
        cudaFuncSetAttribute(attn_kernel,
                             cudaFuncAttributeMaxDynamicSharedMemorySize,
                             ATT_SMEM_BYTES);
        attn_smem_set = 1;
    }

    dim3 blk(256);

    // QKV (headmode B indexing) -> [B,S,H*64]
    dim3 gq(DMODEL / 128, MTOT / 128);           // (8, 32)
    gemm_tf32<<<gq, blk>>>(x, wq, nullptr, q, DMODEL, DMODEL, 0, DMODEL, 0, 1);
    gemm_tf32<<<gq, blk>>>(x, wk, nullptr, k, DMODEL, DMODEL, 0, DMODEL, 0, 1);
    gemm_tf32<<<gq, blk>>>(x, wv, nullptr, v, DMODEL, DMODEL, 0, DMODEL, 0, 1);

    // causal attention -> [B,S,H*64]
    dim3 ga(SEQ / 64, NH, BATCH);                // (32, 16, 2)
    attn_kernel<<<ga, dim3(128), ATT_SMEM_BYTES>>>(q, k, v, attn);

    // output projection
    gemm_tf32<<<gq, blk>>>(attn, w_proj, b_proj, y, DMODEL, DMODEL, DMODEL, DMODEL, 0, 0);

    // x1 = LN(x + y)
    add_ln<<<MTOT, blk>>>(x, y, g1, be1, x1);

    // MLP
    dim3 gm1(FF / 128, MTOT / 128);              // (32, 32)
    gemm_tf32<<<gm1, blk>>>(x1, w1, b1, hbuf, DMODEL, DMODEL, FF, FF, 1, 0);
    dim3 gm2(DMODEL / 128, MTOT / 128);          // (8, 32)
    gemm_tf32<<<gm2, blk>>>(hbuf, w2, b2, y2, FF, FF, DMODEL, DMODEL, 0, 0);

    // out = LN(x1 + y2)
    add_ln<<<MTOT, blk>>>(x1, y2, g2, be2, out);
}

// round 4
// speedup vs baseline: 4.9128x; 1.0386x over previous
#include <cuda_runtime.h>
#include <math.h>

#define SEQ   2048
#define BATCH 2
#define DMODEL 1024
#define NH    16
#define HS    64
#define FF    4096
#define MTOT  (BATCH*SEQ)   /* 4096 rows */

// ---------------- scratch (static device globals; no allocation) ----------------
__device__ float g_q[MTOT*DMODEL];
__device__ float g_k[MTOT*DMODEL];
__device__ float g_v[MTOT*DMODEL];
__device__ float g_attn[MTOT*DMODEL];
__device__ float g_y[MTOT*DMODEL];
__device__ float g_x1[MTOT*DMODEL];
__device__ float g_h[MTOT*FF];
__device__ float g_y2[MTOT*DMODEL];

__device__ __forceinline__ float f2tf32(float x) {
    unsigned r;
    asm("cvt.rna.tf32.f32 %0, %1;" : "=r"(r) : "f"(x));
    return __uint_as_float(r);
}
__device__ __forceinline__ unsigned ld_tf32(const float* p) {
    unsigned r;
    asm("cvt.rna.tf32.f32 %0, %1;" : "=r"(r) : "f"(*p));
    return r;
}
__device__ __forceinline__ void mma_tf32(float* c, const unsigned* a, const unsigned* b) {
    asm volatile(
        "mma.sync.aligned.m16n8k8.row.col.f32.tf32.tf32.f32 "
        "{%0,%1,%2,%3},{%4,%5,%6,%7},{%8,%9},{%0,%1,%2,%3};"
        : "+f"(c[0]), "+f"(c[1]), "+f"(c[2]), "+f"(c[3])
        : "r"(a[0]), "r"(a[1]), "r"(a[2]), "r"(a[3]),
          "r"(b[0]), "r"(b[1]));
}
__device__ __forceinline__ void cp16(float* dst, const float* src) {
    unsigned s = (unsigned)__cvta_generic_to_shared(dst);
    asm volatile("cp.async.cg.shared.global [%0], [%1], 16;" :: "r"(s), "l"(src));
}

// ---------------- tf32 GEMM: 128x128 CTA tile, kchunk 32, 3-stage cp.async ------
// 8 warps 2(M)x4(N), each 64x32 via m16n8k8. smem raw fp32, cvt.rna at frag load.
// headmode: B element (k, n) at B + (n/64)*(K*64) + k*64 + (n%64)
#define AS_FLOATS (128*36)
#define BS_FLOATS (32*136)
#define STG_FLOATS (AS_FLOATS + BS_FLOATS)      /* 8960 */
#define GEMM_SMEM_BYTES (3 * STG_FLOATS * 4)    /* 107520 */

__global__ void __launch_bounds__(256, 2)
gemm_tf32(const float* __restrict__ A, const float* __restrict__ B,
          const float* __restrict__ bias, float* __restrict__ C,
          int K, int lda, int ldb, int ldc, int relu, int headmode)
{
    extern __shared__ float sm[];
    const int tid  = threadIdx.x;
    const int warp = tid >> 5, lane = tid & 31;
    const int wm = warp >> 2, wn = warp & 3;
    const int grp = lane >> 2, thr = lane & 3;
    const int m0 = blockIdx.y * 128;
    const int n0 = blockIdx.x * 128;
    const int nIter = K >> 5;

    auto prefetch = [&](int it) {
        float* As = sm + (it % 3) * STG_FLOATS;
        float* Bs = As + AS_FLOATS;
        const int k0 = it << 5;
#pragma unroll
        for (int i = 0; i < 4; i++) {
            int idx = tid + i * 256;
            int row = idx >> 3, kq = idx & 7;
            cp16(&As[row * 36 + kq * 4],
                 A + (size_t)(m0 + row) * lda + k0 + kq * 4);
        }
#pragma unroll
        for (int i = 0; i < 4; i++) {
            int idx = tid + i * 256;
            int row = idx >> 5, cq = idx & 31;
            int ncol = n0 + cq * 4;
            const float* bp;
            if (headmode)
                bp = B + (size_t)(ncol >> 6) * ((size_t)K * 64)
                       + (size_t)(k0 + row) * 64 + (ncol & 63);
            else
                bp = B + (size_t)(k0 + row) * ldb + ncol;
            cp16(&Bs[row * 136 + cq * 4], bp);
        }
        asm volatile("cp.async.commit_group;");
    };

    prefetch(0);
    if (nIter > 1) prefetch(1);

    float acc[4][4][4];
#pragma unroll
    for (int i = 0; i < 4; i++)
#pragma unroll
        for (int j = 0; j < 4; j++)
#pragma unroll
            for (int c = 0; c < 4; c++) acc[i][j][c] = 0.f;

    for (int it = 0; it < nIter; ++it) {
        if (it == nIter - 1) asm volatile("cp.async.wait_group 0;");
        else                 asm volatile("cp.async.wait_group 1;");
        __syncthreads();
        if (it + 2 < nIter) prefetch(it + 2);

        const float* As = sm + (it % 3) * STG_FLOATS;
        const float* Bs = As + AS_FLOATS;

#pragma unroll
        for (int ks = 0; ks < 4; ks++) {
            const int kk = ks * 8;
            unsigned a[4][4], b[4][2];
#pragma unroll
            for (int i = 0; i < 4; i++) {
                int rm = wm * 64 + i * 16 + grp;
                a[i][0] = ld_tf32(&As[rm * 36 + kk + thr]);
                a[i][1] = ld_tf32(&As[(rm + 8) * 36 + kk + thr]);
                a[i][2] = ld_tf32(&As[rm * 36 + kk + thr + 4]);
                a[i][3] = ld_tf32(&As[(rm + 8) * 36 + kk + thr + 4]);
            }
#pragma unroll
            for (int j = 0; j < 4; j++) {
                int cn = wn * 32 + j * 8 + grp;
                b[j][0] = ld_tf32(&Bs[(kk + thr) * 136 + cn]);
                b[j][1] = ld_tf32(&Bs[(kk + thr + 4) * 136 + cn]);
            }
#pragma unroll
            for (int i = 0; i < 4; i++)
#pragma unroll
                for (int j = 0; j < 4; j++)
                    mma_tf32(acc[i][j], a[i], b[j]);
        }
        __syncthreads();   // all warps done reading stage it before it+2 overwrites
    }

#pragma unroll
    for (int i = 0; i < 4; i++) {
        int row = m0 + wm * 64 + i * 16 + grp;
#pragma unroll
        for (int j = 0; j < 4; j++) {
            int col = n0 + wn * 32 + j * 8 + thr * 2;
            float2 r0 = make_float2(acc[i][j][0], acc[i][j][1]);
            float2 r1 = make_float2(acc[i][j][2], acc[i][j][3]);
            if (bias) {
                float2 bv = *(const float2*)(bias + col);
                r0.x += bv.x; r0.y += bv.y;
                r1.x += bv.x; r1.y += bv.y;
            }
            if (relu) {
                r0.x = fmaxf(r0.x, 0.f); r0.y = fmaxf(r0.y, 0.f);
                r1.x = fmaxf(r1.x, 0.f); r1.y = fmaxf(r1.y, 0.f);
            }
            *(float2*)(C + (size_t)row * ldc + col) = r0;
            *(float2*)(C + (size_t)(row + 8) * ldc + col) = r1;
        }
    }
}

// ---------------- causal flash attention on tensor cores (tf32 mma) -------------
#define ATT_SMEM_BYTES ((64*68 + 64*72 + 64*68) * 4)

__global__ void __launch_bounds__(128)
attn_kernel(const float* __restrict__ q, const float* __restrict__ k,
            const float* __restrict__ v, float* __restrict__ out)
{
    extern __shared__ float dsm[];
    float* Ks = dsm;
    float* Vs = dsm + 64 * 68;
    float* Ps = dsm + 64 * 68 + 64 * 72;

    const int tid  = threadIdx.x;
    const int warp = tid >> 5, lane = tid & 31;
    const int grp = lane >> 2, thr = lane & 3;
    const int b = blockIdx.z, h = blockIdx.y;
    const int q0 = blockIdx.x * 64;
    const float SCALE = 0.125f;

#pragma unroll
    for (int j = 0; j < 8; j++) {
        int lin = tid + j * 128;
        int row = lin >> 4, dq = lin & 15;
        float4 a = *(const float4*)(q + (size_t)(b * SEQ + q0 + row) * DMODEL + h * HS + dq * 4);
        Ps[row * 68 + dq * 4 + 0] = f2tf32(a.x);
        Ps[row * 68 + dq * 4 + 1] = f2tf32(a.y);
        Ps[row * 68 + dq * 4 + 2] = f2tf32(a.z);
        Ps[row * 68 + dq * 4 + 3] = f2tf32(a.w);
    }
    __syncthreads();

    const int rA = warp * 16 + grp;
    unsigned qf[8][4];
#pragma unroll
    for (int ks = 0; ks < 8; ks++) {
        qf[ks][0] = __float_as_uint(Ps[rA * 68 + ks * 8 + thr]);
        qf[ks][1] = __float_as_uint(Ps[(rA + 8) * 68 + ks * 8 + thr]);
        qf[ks][2] = __float_as_uint(Ps[rA * 68 + ks * 8 + thr + 4]);
        qf[ks][3] = __float_as_uint(Ps[(rA + 8) * 68 + ks * 8 + thr + 4]);
    }

    float o[8][4];
#pragma unroll
    for (int j = 0; j < 8; j++)
#pragma unroll
        for (int c = 0; c < 4; c++) o[j][c] = 0.f;
    float m0 = -INFINITY, m1 = -INFINITY, l0 = 0.f, l1 = 0.f;
    const int r0g = q0 + rA, r1g = r0g + 8;
    const int nt = q0 / 64 + 1;

    for (int kt = 0; kt < nt; kt++) {
        const int kt0 = kt * 64;
        __syncthreads();
#pragma unroll
        for (int j = 0; j < 8; j++) {
            int lin = tid + j * 128;
            int key = lin >> 4, dq = lin & 15;
            size_t g = (size_t)(b * SEQ + kt0 + key) * DMODEL + h * HS + dq * 4;
            float4 kv = *(const float4*)(k + g);
            float4 vv = *(const float4*)(v + g);
            Ks[key * 68 + dq * 4 + 0] = f2tf32(kv.x);
            Ks[key * 68 + dq * 4 + 1] = f2tf32(kv.y);
            Ks[key * 68 + dq * 4 + 2] = f2tf32(kv.z);
            Ks[key * 68 + dq * 4 + 3] = f2tf32(kv.w);
            Vs[key * 72 + dq * 4 + 0] = f2tf32(vv.x);
            Vs[key * 72 + dq * 4 + 1] = f2tf32(vv.y);
            Vs[key * 72 + dq * 4 + 2] = f2tf32(vv.z);
            Vs[key * 72 + dq * 4 + 3] = f2tf32(vv.w);
        }
        __syncthreads();

        float s[8][4];
#pragma unroll
        for (int j = 0; j < 8; j++) { s[j][0] = s[j][1] = s[j][2] = s[j][3] = 0.f; }
#pragma unroll
        for (int j = 0; j < 8; j++) {
#pragma unroll
            for (int ks = 0; ks < 8; ks++) {
                unsigned bf[2];
                bf[0] = __float_as_uint(Ks[(j * 8 + grp) * 68 + ks * 8 + thr]);
                bf[1] = __float_as_uint(Ks[(j * 8 + grp) * 68 + ks * 8 + thr + 4]);
                mma_tf32(s[j], qf[ks], bf);
            }
        }

        if (kt == nt - 1) {
#pragma unroll
            for (int j = 0; j < 8; j++) {
                int c0 = kt0 + j * 8 + 2 * thr;
                s[j][0] = (c0     <= r0g) ? s[j][0] * SCALE : -INFINITY;
                s[j][1] = (c0 + 1 <= r0g) ? s[j][1] * SCALE : -INFINITY;
                s[j][2] = (c0     <= r1g) ? s[j][2] * SCALE : -INFINITY;
                s[j][3] = (c0 + 1 <= r1g) ? s[j][3] * SCALE : -INFINITY;
            }
        } else {
#pragma unroll
            for (int j = 0; j < 8; j++) {
                s[j][0] *= SCALE; s[j][1] *= SCALE;
                s[j][2] *= SCALE; s[j][3] *= SCALE;
            }
        }

        float mx0 = -INFINITY, mx1 = -INFINITY;
#pragma unroll
        for (int j = 0; j < 8; j++) {
            mx0 = fmaxf(mx0, fmaxf(s[j][0], s[j][1]));
            mx1 = fmaxf(mx1, fmaxf(s[j][2], s[j][3]));
        }
        mx0 = fmaxf(mx0, __shfl_xor_sync(0xffffffffu, mx0, 1));
        mx0 = fmaxf(mx0, __shfl_xor_sync(0xffffffffu, mx0, 2));
        mx1 = fmaxf(mx1, __shfl_xor_sync(0xffffffffu, mx1, 1));
        mx1 = fmaxf(mx1, __shfl_xor_sync(0xffffffffu, mx1, 2));
        const float mn0 = fmaxf(m0, mx0), mn1 = fmaxf(m1, mx1);
        const float a0 = __expf(m0 - mn0), a1 = __expf(m1 - mn1);
        m0 = mn0; m1 = mn1;

        float ps0 = 0.f, ps1 = 0.f;
#pragma unroll
        for (int j = 0; j < 8; j++) {
            float p00 = __expf(s[j][0] - mn0);
            float p01 = __expf(s[j][1] - mn0);
            float p10 = __expf(s[j][2] - mn1);
            float p11 = __expf(s[j][3] - mn1);
            ps0 += p00 + p01; ps1 += p10 + p11;
            Ps[rA * 68 + j * 8 + 2 * thr]           = f2tf32(p00);
            Ps[rA * 68 + j * 8 + 2 * thr + 1]       = f2tf32(p01);
            Ps[(rA + 8) * 68 + j * 8 + 2 * thr]     = f2tf32(p10);
            Ps[(rA + 8) * 68 + j * 8 + 2 * thr + 1] = f2tf32(p11);
        }
        ps0 += __shfl_xor_sync(0xffffffffu, ps0, 1);
        ps0 += __shfl_xor_sync(0xffffffffu, ps0, 2);
        ps1 += __shfl_xor_sync(0xffffffffu, ps1, 1);
        ps1 += __shfl_xor_sync(0xffffffffu, ps1, 2);
        l0 = l0 * a0 + ps0;
        l1 = l1 * a1 + ps1;

#pragma unroll
        for (int j = 0; j < 8; j++) {
            o[j][0] *= a0; o[j][1] *= a0;
            o[j][2] *= a1; o[j][3] *= a1;
        }
        __syncwarp();

#pragma unroll
        for (int ks = 0; ks < 8; ks++) {
            unsigned pa[4];
            pa[0] = __float_as_uint(Ps[rA * 68 + ks * 8 + thr]);
            pa[1] = __float_as_uint(Ps[(rA + 8) * 68 + ks * 8 + thr]);
            pa[2] = __float_as_uint(Ps[rA * 68 + ks * 8 + thr + 4]);
            pa[3] = __float_as_uint(Ps[(rA + 8) * 68 + ks * 8 + thr + 4]);
#pragma unroll
            for (int j = 0; j < 8; j++) {
                unsigned vb[2];
                vb[0] = __float_as_uint(Vs[(ks * 8 + thr) * 72 + j * 8 + grp]);
                vb[1] = __float_as_uint(Vs[(ks * 8 + thr + 4) * 72 + j * 8 + grp]);
                mma_tf32(o[j], pa, vb);
            }
        }
    }

    const float i0 = 1.f / l0, i1 = 1.f / l1;
    size_t base0 = (size_t)(b * SEQ + r0g) * DMODEL + h * HS;
    size_t base1 = (size_t)(b * SEQ + r1g) * DMODEL + h * HS;
#pragma unroll
    for (int j = 0; j < 8; j++) {
        int col = j * 8 + 2 * thr;
        *(float2*)(out + base0 + col) = make_float2(o[j][0] * i0, o[j][1] * i0);
        *(float2*)(out + base1 + col) = make_float2(o[j][2] * i1, o[j][3] * i1);
    }
}

// ---------------- fused residual + layernorm (one row per block) ----------------
__global__ void __launch_bounds__(256)
add_ln(const float* __restrict__ x, const float* __restrict__ y,
       const float* __restrict__ g, const float* __restrict__ be,
       float* __restrict__ out)
{
    __shared__ float red[256];
    const int row = blockIdx.x, tid = threadIdx.x;
    const size_t base = (size_t)row * DMODEL;
    float4 xv = ((const float4*)(x + base))[tid];
    float4 yv = ((const float4*)(y + base))[tid];
    float v0 = xv.x + yv.x, v1 = xv.y + yv.y, v2 = xv.z + yv.z, v3 = xv.w + yv.w;

    red[tid] = v0 + v1 + v2 + v3;
    __syncthreads();
    for (int s = 128; s > 0; s >>= 1) {
        if (tid < s) red[tid] += red[tid + s];
        __syncthreads();
    }
    const float mu = red[0] * (1.f / DMODEL);
    __syncthreads();

    float d0 = v0 - mu, d1 = v1 - mu, d2 = v2 - mu, d3 = v3 - mu;
    red[tid] = d0 * d0 + d1 * d1 + d2 * d2 + d3 * d3;
    __syncthreads();
    for (int s = 128; s > 0; s >>= 1) {
        if (tid < s) red[tid] += red[tid + s];
        __syncthreads();
    }
    const float rstd = rsqrtf(red[0] * (1.f / DMODEL) + 1e-5f);

    float4 gv = ((const float4*)g)[tid];
    float4 bv = ((const float4*)be)[tid];
    float4 oo;
    oo.x = d0 * rstd * gv.x + bv.x;
    oo.y = d1 * rstd * gv.y + bv.y;
    oo.z = d2 * rstd * gv.z + bv.z;
    oo.w = d3 * rstd * gv.w + bv.w;
    ((float4*)(out + base))[tid] = oo;
}

// ---------------- host driver ----------------
extern "C" void kernel_launch(void* const* d_in, const int* in_sizes, int n_in,
                              void* d_out, int out_size)
{
    const float* x      = (const float*)d_in[0];
    const float* wq     = (const float*)d_in[1];
    const float* wk     = (const float*)d_in[2];
    const float* wv     = (const float*)d_in[3];
    const float* w_proj = (const float*)d_in[4];
    const float* b_proj = (const float*)d_in[5];
    const float* w1     = (const float*)d_in[6];
    const float* b1     = (const float*)d_in[7];
    const float* w2     = (const float*)d_in[8];
    const float* b2     = (const float*)d_in[9];
    const float* g1     = (const float*)d_in[10];
    const float* be1    = (const float*)d_in[11];
    const float* g2     = (const float*)d_in[12];
    const float* be2    = (const float*)d_in[13];
    float* out = (float*)d_out;

    float *q, *k, *v, *attn, *y, *x1, *hbuf, *y2;
    cudaGetSymbolAddress((void**)&q,    g_q);
    cudaGetSymbolAddress((void**)&k,    g_k);
    cudaGetSymbolAddress((void**)&v,    g_v);
    cudaGetSymbolAddress((void**)&attn, g_attn);
    cudaGetSymbolAddress((void**)&y,    g_y);
    cudaGetSymbolAddress((void**)&x1,   g_x1);
    cudaGetSymbolAddress((void**)&hbuf, g_h);
    cudaGetSymbolAddress((void**)&y2,   g_y2);

    cudaFuncSetAttribute(attn_kernel,
                         cudaFuncAttributeMaxDynamicSharedMemorySize,
                         ATT_SMEM_BYTES);
    cudaFuncSetAttribute(gemm_tf32,
                         cudaFuncAttributeMaxDynamicSharedMemorySize,
                         GEMM_SMEM_BYTES);

    dim3 blk(256);

    // QKV (headmode B indexing) -> [B,S,H*64]
    dim3 gq(DMODEL / 128, MTOT / 128);           // (8, 32)
    gemm_tf32<<<gq, blk, GEMM_SMEM_BYTES>>>(x, wq, nullptr, q, DMODEL, DMODEL, 0, DMODEL, 0, 1);
    gemm_tf32<<<gq, blk, GEMM_SMEM_BYTES>>>(x, wk, nullptr, k, DMODEL, DMODEL, 0, DMODEL, 0, 1);
    gemm_tf32<<<gq, blk, GEMM_SMEM_BYTES>>>(x, wv, nullptr, v, DMODEL, DMODEL, 0, DMODEL, 0, 1);

    // causal attention -> [B,S,H*64]
    dim3 ga(SEQ / 64, NH, BATCH);                // (32, 16, 2)
    attn_kernel<<<ga, dim3(128), ATT_SMEM_BYTES>>>(q, k, v, attn);

    // output projection
    gemm_tf32<<<gq, blk, GEMM_SMEM_BYTES>>>(attn, w_proj, b_proj, y, DMODEL, DMODEL, DMODEL, DMODEL, 0, 0);

    // x1 = LN(x + y)
    add_ln<<<MTOT, blk>>>(x, y, g1, be1, x1);

    // MLP
    dim3 gm1(FF / 128, MTOT / 128);              // (32, 32)
    gemm_tf32<<<gm1, blk, GEMM_SMEM_BYTES>>>(x1, w1, b1, hbuf, DMODEL, DMODEL, FF, FF, 1, 0);
    dim3 gm2(DMODEL / 128, MTOT / 128);          // (8, 32)
    gemm_tf32<<<gm2, blk, GEMM_SMEM_BYTES>>>(hbuf, w2, b2, y2, FF, FF, DMODEL, DMODEL, 0, 0);

    // out = LN(x1 + y2)
    add_ln<<<MTOT, blk>>>(x1, y2, g2, be2, out);
}

// round 5
// speedup vs baseline: 5.4231x; 1.1039x over previous
#include <cuda_runtime.h>
#include <math.h>

#define SEQ   2048
#define BATCH 2
#define DMODEL 1024
#define NH    16
#define HS    64
#define FF    4096
#define MTOT  (BATCH*SEQ)   /* 4096 rows */

// ---------------- scratch (static device globals; no allocation) ----------------
__device__ float g_q[MTOT*DMODEL];
__device__ float g_k[MTOT*DMODEL];
__device__ float g_v[MTOT*DMODEL];
__device__ float g_attn[MTOT*DMODEL];
__device__ float g_y[MTOT*DMODEL];
__device__ float g_x1[MTOT*DMODEL];
__device__ float g_h[MTOT*FF];
__device__ float g_y2[MTOT*DMODEL];

__device__ __forceinline__ float f2tf32(float x) {
    unsigned r;
    asm("cvt.rna.tf32.f32 %0, %1;" : "=r"(r) : "f"(x));
    return __uint_as_float(r);
}
__device__ __forceinline__ unsigned ld_tf32(const float* p) {
    unsigned r;
    asm("cvt.rna.tf32.f32 %0, %1;" : "=r"(r) : "f"(*p));
    return r;
}
__device__ __forceinline__ void mma_tf32(float* c, const unsigned* a, const unsigned* b) {
    asm volatile(
        "mma.sync.aligned.m16n8k8.row.col.f32.tf32.tf32.f32 "
        "{%0,%1,%2,%3},{%4,%5,%6,%7},{%8,%9},{%0,%1,%2,%3};"
        : "+f"(c[0]), "+f"(c[1]), "+f"(c[2]), "+f"(c[3])
        : "r"(a[0]), "r"(a[1]), "r"(a[2]), "r"(a[3]),
          "r"(b[0]), "r"(b[1]));
}
__device__ __forceinline__ void cp16(float* dst, const float* src) {
    unsigned s = (unsigned)__cvta_generic_to_shared(dst);
    asm volatile("cp.async.cg.shared.global [%0], [%1], 16;" :: "r"(s), "l"(src));
}

// ---------------- tf32 GEMM: 128x128 CTA tile, kchunk 32, 2-stage cp.async ------
// 8 warps 2(M)x4(N), each 64x32 via m16n8k8. smem raw fp32, cvt.rna at frag load.
// 2 stages x 35840B = 71680B/CTA -> 2 CTAs/SM resident.
// headmode: B element (k, n) at B + (n/64)*(K*64) + k*64 + (n%64)
#define AS_FLOATS (128*36)
#define BS_FLOATS (32*136)
#define STG_FLOATS (AS_FLOATS + BS_FLOATS)      /* 8960 */
#define GEMM_SMEM_BYTES (2 * STG_FLOATS * 4)    /* 71680 */

__global__ void __launch_bounds__(256, 2)
gemm_tf32(const float* __restrict__ A, const float* __restrict__ B,
          const float* __restrict__ bias, float* __restrict__ C,
          int K, int lda, int ldb, int ldc, int relu, int headmode)
{
    extern __shared__ float sm[];
    const int tid  = threadIdx.x;
    const int warp = tid >> 5, lane = tid & 31;
    const int wm = warp >> 2, wn = warp & 3;
    const int grp = lane >> 2, thr = lane & 3;
    const int m0 = blockIdx.y * 128;
    const int n0 = blockIdx.x * 128;
    const int nIter = K >> 5;

    auto prefetch = [&](int it) {
        float* As = sm + (it & 1) * STG_FLOATS;
        float* Bs = As + AS_FLOATS;
        const int k0 = it << 5;
#pragma unroll
        for (int i = 0; i < 4; i++) {
            int idx = tid + i * 256;
            int row = idx >> 3, kq = idx & 7;
            cp16(&As[row * 36 + kq * 4],
                 A + (size_t)(m0 + row) * lda + k0 + kq * 4);
        }
#pragma unroll
        for (int i = 0; i < 4; i++) {
            int idx = tid + i * 256;
            int row = idx >> 5, cq = idx & 31;
            int ncol = n0 + cq * 4;
            const float* bp;
            if (headmode)
                bp = B + (size_t)(ncol >> 6) * ((size_t)K * 64)
                       + (size_t)(k0 + row) * 64 + (ncol & 63);
            else
                bp = B + (size_t)(k0 + row) * ldb + ncol;
            cp16(&Bs[row * 136 + cq * 4], bp);
        }
        asm volatile("cp.async.commit_group;");
    };

    prefetch(0);

    float acc[4][4][4];
#pragma unroll
    for (int i = 0; i < 4; i++)
#pragma unroll
        for (int j = 0; j < 4; j++)
#pragma unroll
            for (int c = 0; c < 4; c++) acc[i][j][c] = 0.f;

    for (int it = 0; it < nIter; ++it) {
        // issue next tile's loads into the other buffer (free: consumed 2 iters ago)
        if (it + 1 < nIter) {
            prefetch(it + 1);
            asm volatile("cp.async.wait_group 1;");  // stage `it` complete
        } else {
            asm volatile("cp.async.wait_group 0;");
        }
        __syncthreads();

        const float* As = sm + (it & 1) * STG_FLOATS;
        const float* Bs = As + AS_FLOATS;

#pragma unroll
        for (int ks = 0; ks < 4; ks++) {
            const int kk = ks * 8;
            unsigned a[4][4], b[4][2];
#pragma unroll
            for (int i = 0; i < 4; i++) {
                int rm = wm * 64 + i * 16 + grp;
                a[i][0] = ld_tf32(&As[rm * 36 + kk + thr]);
                a[i][1] = ld_tf32(&As[(rm + 8) * 36 + kk + thr]);
                a[i][2] = ld_tf32(&As[rm * 36 + kk + thr + 4]);
                a[i][3] = ld_tf32(&As[(rm + 8) * 36 + kk + thr + 4]);
            }
#pragma unroll
            for (int j = 0; j < 4; j++) {
                int cn = wn * 32 + j * 8 + grp;
                b[j][0] = ld_tf32(&Bs[(kk + thr) * 136 + cn]);
                b[j][1] = ld_tf32(&Bs[(kk + thr + 4) * 136 + cn]);
            }
#pragma unroll
            for (int i = 0; i < 4; i++)
#pragma unroll
                for (int j = 0; j < 4; j++)
                    mma_tf32(acc[i][j], a[i], b[j]);
        }
        __syncthreads();   // stage `it` fully consumed before it+2 overwrites
    }

#pragma unroll
    for (int i = 0; i < 4; i++) {
        int row = m0 + wm * 64 + i * 16 + grp;
#pragma unroll
        for (int j = 0; j < 4; j++) {
            int col = n0 + wn * 32 + j * 8 + thr * 2;
            float2 r0 = make_float2(acc[i][j][0], acc[i][j][1]);
            float2 r1 = make_float2(acc[i][j][2], acc[i][j][3]);
            if (bias) {
                float2 bv = *(const float2*)(bias + col);
                r0.x += bv.x; r0.y += bv.y;
                r1.x += bv.x; r1.y += bv.y;
            }
            if (relu) {
                r0.x = fmaxf(r0.x, 0.f); r0.y = fmaxf(r0.y, 0.f);
                r1.x = fmaxf(r1.x, 0.f); r1.y = fmaxf(r1.y, 0.f);
            }
            *(float2*)(C + (size_t)row * ldc + col) = r0;
            *(float2*)(C + (size_t)(row + 8) * ldc + col) = r1;
        }
    }
}

// ---------------- causal flash attention on tensor cores (tf32 mma) -------------
#define ATT_SMEM_BYTES ((64*68 + 64*72 + 64*68) * 4)

__global__ void __launch_bounds__(128)
attn_kernel(const float* __restrict__ q, const float* __restrict__ k,
            const float* __restrict__ v, float* __restrict__ out)
{
    extern __shared__ float dsm[];
    float* Ks = dsm;
    float* Vs = dsm + 64 * 68;
    float* Ps = dsm + 64 * 68 + 64 * 72;

    const int tid  = threadIdx.x;
    const int warp = tid >> 5, lane = tid & 31;
    const int grp = lane >> 2, thr = lane & 3;
    const int b = blockIdx.z, h = blockIdx.y;
    const int q0 = blockIdx.x * 64;
    const float SCALE = 0.125f;

#pragma unroll
    for (int j = 0; j < 8; j++) {
        int lin = tid + j * 128;
        int row = lin >> 4, dq = lin & 15;
        float4 a = *(const float4*)(q + (size_t)(b * SEQ + q0 + row) * DMODEL + h * HS + dq * 4);
        Ps[row * 68 + dq * 4 + 0] = f2tf32(a.x);
        Ps[row * 68 + dq * 4 + 1] = f2tf32(a.y);
        Ps[row * 68 + dq * 4 + 2] = f2tf32(a.z);
        Ps[row * 68 + dq * 4 + 3] = f2tf32(a.w);
    }
    __syncthreads();

    const int rA = warp * 16 + grp;
    unsigned qf[8][4];
#pragma unroll
    for (int ks = 0; ks < 8; ks++) {
        qf[ks][0] = __float_as_uint(Ps[rA * 68 + ks * 8 + thr]);
        qf[ks][1] = __float_as_uint(Ps[(rA + 8) * 68 + ks * 8 + thr]);
        qf[ks][2] = __float_as_uint(Ps[rA * 68 + ks * 8 + thr + 4]);
        qf[ks][3] = __float_as_uint(Ps[(rA + 8) * 68 + ks * 8 + thr + 4]);
    }

    float o[8][4];
#pragma unroll
    for (int j = 0; j < 8; j++)
#pragma unroll
        for (int c = 0; c < 4; c++) o[j][c] = 0.f;
    float m0 = -INFINITY, m1 = -INFINITY, l0 = 0.f, l1 = 0.f;
    const int r0g = q0 + rA, r1g = r0g + 8;
    const int nt = q0 / 64 + 1;

    for (int kt = 0; kt < nt; kt++) {
        const int kt0 = kt * 64;
        __syncthreads();
#pragma unroll
        for (int j = 0; j < 8; j++) {
            int lin = tid + j * 128;
            int key = lin >> 4, dq = lin & 15;
            size_t g = (size_t)(b * SEQ + kt0 + key) * DMODEL + h * HS + dq * 4;
            float4 kv = *(const float4*)(k + g);
            float4 vv = *(const float4*)(v + g);
            Ks[key * 68 + dq * 4 + 0] = f2tf32(kv.x);
            Ks[key * 68 + dq * 4 + 1] = f2tf32(kv.y);
            Ks[key * 68 + dq * 4 + 2] = f2tf32(kv.z);
            Ks[key * 68 + dq * 4 + 3] = f2tf32(kv.w);
            Vs[key * 72 + dq * 4 + 0] = f2tf32(vv.x);
            Vs[key * 72 + dq * 4 + 1] = f2tf32(vv.y);
            Vs[key * 72 + dq * 4 + 2] = f2tf32(vv.z);
            Vs[key * 72 + dq * 4 + 3] = f2tf32(vv.w);
        }
        __syncthreads();

        float s[8][4];
#pragma unroll
        for (int j = 0; j < 8; j++) { s[j][0] = s[j][1] = s[j][2] = s[j][3] = 0.f; }
#pragma unroll
        for (int j = 0; j < 8; j++) {
#pragma unroll
            for (int ks = 0; ks < 8; ks++) {
                unsigned bf[2];
                bf[0] = __float_as_uint(Ks[(j * 8 + grp) * 68 + ks * 8 + thr]);
                bf[1] = __float_as_uint(Ks[(j * 8 + grp) * 68 + ks * 8 + thr + 4]);
                mma_tf32(s[j], qf[ks], bf);
            }
        }

        if (kt == nt - 1) {
#pragma unroll
            for (int j = 0; j < 8; j++) {
                int c0 = kt0 + j * 8 + 2 * thr;
                s[j][0] = (c0     <= r0g) ? s[j][0] * SCALE : -INFINITY;
                s[j][1] = (c0 + 1 <= r0g) ? s[j][1] * SCALE : -INFINITY;
                s[j][2] = (c0     <= r1g) ? s[j][2] * SCALE : -INFINITY;
                s[j][3] = (c0 + 1 <= r1g) ? s[j][3] * SCALE : -INFINITY;
            }
        } else {
#pragma unroll
            for (int j = 0; j < 8; j++) {
                s[j][0] *= SCALE; s[j][1] *= SCALE;
                s[j][2] *= SCALE; s[j][3] *= SCALE;
            }
        }

        float mx0 = -INFINITY, mx1 = -INFINITY;
#pragma unroll
        for (int j = 0; j < 8; j++) {
            mx0 = fmaxf(mx0, fmaxf(s[j][0], s[j][1]));
            mx1 = fmaxf(mx1, fmaxf(s[j][2], s[j][3]));
        }
        mx0 = fmaxf(mx0, __shfl_xor_sync(0xffffffffu, mx0, 1));
        mx0 = fmaxf(mx0, __shfl_xor_sync(0xffffffffu, mx0, 2));
        mx1 = fmaxf(mx1, __shfl_xor_sync(0xffffffffu, mx1, 1));
        mx1 = fmaxf(mx1, __shfl_xor_sync(0xffffffffu, mx1, 2));
        const float mn0 = fmaxf(m0, mx0), mn1 = fmaxf(m1, mx1);
        const float a0 = __expf(m0 - mn0), a1 = __expf(m1 - mn1);
        m0 = mn0; m1 = mn1;

        float ps0 = 0.f, ps1 = 0.f;
#pragma unroll
        for (int j = 0; j < 8; j++) {
            float p00 = __expf(s[j][0] - mn0);
            float p01 = __expf(s[j][1] - mn0);
            float p10 = __expf(s[j][2] - mn1);
            float p11 = __expf(s[j][3] - mn1);
            ps0 += p00 + p01; ps1 += p10 + p11;
            Ps[rA * 68 + j * 8 + 2 * thr]           = f2tf32(p00);
            Ps[rA * 68 + j * 8 + 2 * thr + 1]       = f2tf32(p01);
            Ps[(rA + 8) * 68 + j * 8 + 2 * thr]     = f2tf32(p10);
            Ps[(rA + 8) * 68 + j * 8 + 2 * thr + 1] = f2tf32(p11);
        }
        ps0 += __shfl_xor_sync(0xffffffffu, ps0, 1);
        ps0 += __shfl_xor_sync(0xffffffffu, ps0, 2);
        ps1 += __shfl_xor_sync(0xffffffffu, ps1, 1);
        ps1 += __shfl_xor_sync(0xffffffffu, ps1, 2);
        l0 = l0 * a0 + ps0;
        l1 = l1 * a1 + ps1;

#pragma unroll
        for (int j = 0; j < 8; j++) {
            o[j][0] *= a0; o[j][1] *= a0;
            o[j][2] *= a1; o[j][3] *= a1;
        }
        __syncwarp();

#pragma unroll
        for (int ks = 0; ks < 8; ks++) {
            unsigned pa[4];
            pa[0] = __float_as_uint(Ps[rA * 68 + ks * 8 + thr]);
            pa[1] = __float_as_uint(Ps[(rA + 8) * 68 + ks * 8 + thr]);
            pa[2] = __float_as_uint(Ps[rA * 68 + ks * 8 + thr + 4]);
            pa[3] = __float_as_uint(Ps[(rA + 8) * 68 + ks * 8 + thr + 4]);
#pragma unroll
            for (int j = 0; j < 8; j++) {
                unsigned vb[2];
                vb[0] = __float_as_uint(Vs[(ks * 8 + thr) * 72 + j * 8 + grp]);
                vb[1] = __float_as_uint(Vs[(ks * 8 + thr + 4) * 72 + j * 8 + grp]);
                mma_tf32(o[j], pa, vb);
            }
        }
    }

    const float i0 = 1.f / l0, i1 = 1.f / l1;
    size_t base0 = (size_t)(b * SEQ + r0g) * DMODEL + h * HS;
    size_t base1 = (size_t)(b * SEQ + r1g) * DMODEL + h * HS;
#pragma unroll
    for (int j = 0; j < 8; j++) {
        int col = j * 8 + 2 * thr;
        *(float2*)(out + base0 + col) = make_float2(o[j][0] * i0, o[j][1] * i0);
        *(float2*)(out + base1 + col) = make_float2(o[j][2] * i1, o[j][3] * i1);
    }
}

// ---------------- fused residual + layernorm (one row per block) ----------------
__global__ void __launch_bounds__(256)
add_ln(const float* __restrict__ x, const float* __restrict__ y,
       const float* __restrict__ g, const float* __restrict__ be,
       float* __restrict__ out)
{
    __shared__ float red[256];
    const int row = blockIdx.x, tid = threadIdx.x;
    const size_t base = (size_t)row * DMODEL;
    float4 xv = ((const float4*)(x + base))[tid];
    float4 yv = ((const float4*)(y + base))[tid];
    float v0 = xv.x + yv.x, v1 = xv.y + yv.y, v2 = xv.z + yv.z, v3 = xv.w + yv.w;

    red[tid] = v0 + v1 + v2 + v3;
    __syncthreads();
    for (int s = 128; s > 0; s >>= 1) {
        if (tid < s) red[tid] += red[tid + s];
        __syncthreads();
    }
    const float mu = red[0] * (1.f / DMODEL);
    __syncthreads();

    float d0 = v0 - mu, d1 = v1 - mu, d2 = v2 - mu, d3 = v3 - mu;
    red[tid] = d0 * d0 + d1 * d1 + d2 * d2 + d3 * d3;
    __syncthreads();
    for (int s = 128; s > 0; s >>= 1) {
        if (tid < s) red[tid] += red[tid + s];
        __syncthreads();
    }
    const float rstd = rsqrtf(red[0] * (1.f / DMODEL) + 1e-5f);

    float4 gv = ((const float4*)g)[tid];
    float4 bv = ((const float4*)be)[tid];
    float4 oo;
    oo.x = d0 * rstd * gv.x + bv.x;
    oo.y = d1 * rstd * gv.y + bv.y;
    oo.z = d2 * rstd * gv.z + bv.z;
    oo.w = d3 * rstd * gv.w + bv.w;
    ((float4*)(out + base))[tid] = oo;
}

// ---------------- host driver ----------------
extern "C" void kernel_launch(void* const* d_in, const int* in_sizes, int n_in,
                              void* d_out, int out_size)
{
    const float* x      = (const float*)d_in[0];
    const float* wq     = (const float*)d_in[1];
    const float* wk     = (const float*)d_in[2];
    const float* wv     = (const float*)d_in[3];
    const float* w_proj = (const float*)d_in[4];
    const float* b_proj = (const float*)d_in[5];
    const float* w1     = (const float*)d_in[6];
    const float* b1     = (const float*)d_in[7];
    const float* w2     = (const float*)d_in[8];
    const float* b2     = (const float*)d_in[9];
    const float* g1     = (const float*)d_in[10];
    const float* be1    = (const float*)d_in[11];
    const float* g2     = (const float*)d_in[12];
    const float* be2    = (const float*)d_in[13];
    float* out = (float*)d_out;

    float *q, *k, *v, *attn, *y, *x1, *hbuf, *y2;
    cudaGetSymbolAddress((void**)&q,    g_q);
    cudaGetSymbolAddress((void**)&k,    g_k);
    cudaGetSymbolAddress((void**)&v,    g_v);
    cudaGetSymbolAddress((void**)&attn, g_attn);
    cudaGetSymbolAddress((void**)&y,    g_y);
    cudaGetSymbolAddress((void**)&x1,   g_x1);
    cudaGetSymbolAddress((void**)&hbuf, g_h);
    cudaGetSymbolAddress((void**)&y2,   g_y2);

    cudaFuncSetAttribute(attn_kernel,
                         cudaFuncAttributeMaxDynamicSharedMemorySize,
                         ATT_SMEM_BYTES);
    cudaFuncSetAttribute(gemm_tf32,
                         cudaFuncAttributeMaxDynamicSharedMemorySize,
                         GEMM_SMEM_BYTES);

    dim3 blk(256);

    // QKV (headmode B indexing) -> [B,S,H*64]
    dim3 gq(DMODEL / 128, MTOT / 128);           // (8, 32)
    gemm_tf32<<<gq, blk, GEMM_SMEM_BYTES>>>(x, wq, nullptr, q, DMODEL, DMODEL, 0, DMODEL, 0, 1);
    gemm_tf32<<<gq, blk, GEMM_SMEM_BYTES>>>(x, wk, nullptr, k, DMODEL, DMODEL, 0, DMODEL, 0, 1);
    gemm_tf32<<<gq, blk, GEMM_SMEM_BYTES>>>(x, wv, nullptr, v, DMODEL, DMODEL, 0, DMODEL, 0, 1);

    // causal attention -> [B,S,H*64]
    dim3 ga(SEQ / 64, NH, BATCH);                // (32, 16, 2)
    attn_kernel<<<ga, dim3(128), ATT_SMEM_BYTES>>>(q, k, v, attn);

    // output projection
    gemm_tf32<<<gq, blk, GEMM_SMEM_BYTES>>>(attn, w_proj, b_proj, y, DMODEL, DMODEL, DMODEL, DMODEL, 0, 0);

    // x1 = LN(x + y)
    add_ln<<<MTOT, blk>>>(x, y, g1, be1, x1);

    // MLP
    dim3 gm1(FF / 128, MTOT / 128);              // (32, 32)
    gemm_tf32<<<gm1, blk, GEMM_SMEM_BYTES>>>(x1, w1, b1, hbuf, DMODEL, DMODEL, FF, FF, 1, 0);
    dim3 gm2(DMODEL / 128, MTOT / 128);          // (8, 32)
    gemm_tf32<<<gm2, blk, GEMM_SMEM_BYTES>>>(hbuf, w2, b2, y2, FF, FF, DMODEL, DMODEL, 0, 0);

    // out = LN(x1 + y2)
    add_ln<<<MTOT, blk>>>(x1, y2, g2, be2, out);
}

// round 6
// speedup vs baseline: 5.5336x; 1.0204x over previous
#include <cuda_runtime.h>
#include <math.h>

#define SEQ   2048
#define BATCH 2
#define DMODEL 1024
#define NH    16
#define HS    64
#define FF    4096
#define MTOT  (BATCH*SEQ)   /* 4096 rows */

// ---------------- scratch (static device globals; no allocation) ----------------
__device__ float g_q[MTOT*DMODEL];
__device__ float g_k[MTOT*DMODEL];
__device__ float g_v[MTOT*DMODEL];
__device__ float g_attn[MTOT*DMODEL];
__device__ float g_y[MTOT*DMODEL];
__device__ float g_x1[MTOT*DMODEL];
__device__ float g_h[MTOT*FF];
__device__ float g_y2[MTOT*DMODEL];

__device__ __forceinline__ float f2tf32(float x) {
    unsigned r;
    asm("cvt.rna.tf32.f32 %0, %1;" : "=r"(r) : "f"(x));
    return __uint_as_float(r);
}
__device__ __forceinline__ unsigned ld_tf32(const float* p) {
    unsigned r;
    asm("cvt.rna.tf32.f32 %0, %1;" : "=r"(r) : "f"(*p));
    return r;
}
__device__ __forceinline__ void mma_tf32(float* c, const unsigned* a, const unsigned* b) {
    asm volatile(
        "mma.sync.aligned.m16n8k8.row.col.f32.tf32.tf32.f32 "
        "{%0,%1,%2,%3},{%4,%5,%6,%7},{%8,%9},{%0,%1,%2,%3};"
        : "+f"(c[0]), "+f"(c[1]), "+f"(c[2]), "+f"(c[3])
        : "r"(a[0]), "r"(a[1]), "r"(a[2]), "r"(a[3]),
          "r"(b[0]), "r"(b[1]));
}
__device__ __forceinline__ void cp16(float* dst, const float* src) {
    unsigned s = (unsigned)__cvta_generic_to_shared(dst);
    asm volatile("cp.async.cg.shared.global [%0], [%1], 16;" :: "r"(s), "l"(src));
}

// ---------------- tf32 GEMM core: 128x128 CTA tile, 4 warps x 64x64, kchunk 32 --
// 2-stage cp.async. smem raw fp32, cvt.rna at fragment load.
// headmode: B element (k, n) at B + (n/64)*(K*64) + k*64 + (n%64)
#define AS_FLOATS (128*36)
#define BS_FLOATS (32*136)
#define STG_FLOATS (AS_FLOATS + BS_FLOATS)      /* 8960 */
#define GEMM_SMEM_BYTES (2 * STG_FLOATS * 4)    /* 71680 */

__device__ __forceinline__ void
gemm_core(const float* __restrict__ A, const float* __restrict__ B,
          const float* __restrict__ bias, float* __restrict__ C,
          int K, int lda, int ldb, int ldc, int relu, int headmode,
          int m0, int n0, float* sm)
{
    const int tid  = threadIdx.x;
    const int warp = tid >> 5, lane = tid & 31;
    const int wm = warp >> 1, wn = warp & 1;
    const int grp = lane >> 2, thr = lane & 3;
    const int nIter = K >> 5;

    auto prefetch = [&](int it) {
        float* As = sm + (it & 1) * STG_FLOATS;
        float* Bs = As + AS_FLOATS;
        const int k0 = it << 5;
#pragma unroll
        for (int i = 0; i < 8; i++) {
            int idx = tid + i * 128;          // 0..1023 float4s of A tile
            int row = idx >> 3, kq = idx & 7;
            cp16(&As[row * 36 + kq * 4],
                 A + (size_t)(m0 + row) * lda + k0 + kq * 4);
        }
#pragma unroll
        for (int i = 0; i < 8; i++) {
            int idx = tid + i * 128;          // 0..1023 float4s of B tile
            int row = idx >> 5, cq = idx & 31;
            int ncol = n0 + cq * 4;
            const float* bp;
            if (headmode)
                bp = B + (size_t)(ncol >> 6) * ((size_t)K * 64)
                       + (size_t)(k0 + row) * 64 + (ncol & 63);
            else
                bp = B + (size_t)(k0 + row) * ldb + ncol;
            cp16(&Bs[row * 136 + cq * 4], bp);
        }
        asm volatile("cp.async.commit_group;");
    };

    prefetch(0);

    float acc[4][8][4];
#pragma unroll
    for (int i = 0; i < 4; i++)
#pragma unroll
        for (int j = 0; j < 8; j++)
#pragma unroll
            for (int c = 0; c < 4; c++) acc[i][j][c] = 0.f;

    for (int it = 0; it < nIter; ++it) {
        if (it + 1 < nIter) {
            prefetch(it + 1);
            asm volatile("cp.async.wait_group 1;");
        } else {
            asm volatile("cp.async.wait_group 0;");
        }
        __syncthreads();

        const float* As = sm + (it & 1) * STG_FLOATS;
        const float* Bs = As + AS_FLOATS;

#pragma unroll
        for (int ks = 0; ks < 4; ks++) {
            const int kk = ks * 8;
            unsigned a[4][4], b[8][2];
#pragma unroll
            for (int i = 0; i < 4; i++) {
                int rm = wm * 64 + i * 16 + grp;
                a[i][0] = ld_tf32(&As[rm * 36 + kk + thr]);
                a[i][1] = ld_tf32(&As[(rm + 8) * 36 + kk + thr]);
                a[i][2] = ld_tf32(&As[rm * 36 + kk + thr + 4]);
                a[i][3] = ld_tf32(&As[(rm + 8) * 36 + kk + thr + 4]);
            }
#pragma unroll
            for (int j = 0; j < 8; j++) {
                int cn = wn * 64 + j * 8 + grp;
                b[j][0] = ld_tf32(&Bs[(kk + thr) * 136 + cn]);
                b[j][1] = ld_tf32(&Bs[(kk + thr + 4) * 136 + cn]);
            }
#pragma unroll
            for (int i = 0; i < 4; i++)
#pragma unroll
                for (int j = 0; j < 8; j++)
                    mma_tf32(acc[i][j], a[i], b[j]);
        }
        __syncthreads();
    }

#pragma unroll
    for (int i = 0; i < 4; i++) {
        int row = m0 + wm * 64 + i * 16 + grp;
#pragma unroll
        for (int j = 0; j < 8; j++) {
            int col = n0 + wn * 64 + j * 8 + thr * 2;
            float2 r0 = make_float2(acc[i][j][0], acc[i][j][1]);
            float2 r1 = make_float2(acc[i][j][2], acc[i][j][3]);
            if (bias) {
                float2 bv = *(const float2*)(bias + col);
                r0.x += bv.x; r0.y += bv.y;
                r1.x += bv.x; r1.y += bv.y;
            }
            if (relu) {
                r0.x = fmaxf(r0.x, 0.f); r0.y = fmaxf(r0.y, 0.f);
                r1.x = fmaxf(r1.x, 0.f); r1.y = fmaxf(r1.y, 0.f);
            }
            *(float2*)(C + (size_t)row * ldc + col) = r0;
            *(float2*)(C + (size_t)(row + 8) * ldc + col) = r1;
        }
    }
}

__global__ void __launch_bounds__(128, 2)
gemm_tf32(const float* __restrict__ A, const float* __restrict__ B,
          const float* __restrict__ bias, float* __restrict__ C,
          int K, int lda, int ldb, int ldc, int relu, int headmode)
{
    extern __shared__ float sm[];
    gemm_core(A, B, bias, C, K, lda, ldb, ldc, relu, headmode,
              blockIdx.y * 128, blockIdx.x * 128, sm);
}

// fused QKV: blockIdx.z selects (weight, output) pair; headmode indexing
__global__ void __launch_bounds__(128, 2)
gemm_qkv(const float* __restrict__ x,
         const float* __restrict__ wq, const float* __restrict__ wk,
         const float* __restrict__ wv,
         float* __restrict__ q, float* __restrict__ k, float* __restrict__ v)
{
    extern __shared__ float sm[];
    const float* B = (blockIdx.z == 0) ? wq : (blockIdx.z == 1) ? wk : wv;
    float*       C = (blockIdx.z == 0) ? q  : (blockIdx.z == 1) ? k  : v;
    gemm_core(x, B, nullptr, C, DMODEL, DMODEL, 0, DMODEL, 0, 1,
              blockIdx.y * 128, blockIdx.x * 128, sm);
}

// ---------------- causal flash attention on tensor cores (tf32 mma) -------------
#define ATT_SMEM_BYTES ((64*68 + 64*72 + 64*68) * 4)

__global__ void __launch_bounds__(128)
attn_kernel(const float* __restrict__ q, const float* __restrict__ k,
            const float* __restrict__ v, float* __restrict__ out)
{
    extern __shared__ float dsm[];
    float* Ks = dsm;
    float* Vs = dsm + 64 * 68;
    float* Ps = dsm + 64 * 68 + 64 * 72;

    const int tid  = threadIdx.x;
    const int warp = tid >> 5, lane = tid & 31;
    const int grp = lane >> 2, thr = lane & 3;
    const int b = blockIdx.z, h = blockIdx.y;
    const int q0 = blockIdx.x * 64;
    const float SCALE = 0.125f;

#pragma unroll
    for (int j = 0; j < 8; j++) {
        int lin = tid + j * 128;
        int row = lin >> 4, dq = lin & 15;
        float4 a = *(const float4*)(q + (size_t)(b * SEQ + q0 + row) * DMODEL + h * HS + dq * 4);
        Ps[row * 68 + dq * 4 + 0] = f2tf32(a.x);
        Ps[row * 68 + dq * 4 + 1] = f2tf32(a.y);
        Ps[row * 68 + dq * 4 + 2] = f2tf32(a.z);
        Ps[row * 68 + dq * 4 + 3] = f2tf32(a.w);
    }
    __syncthreads();

    const int rA = warp * 16 + grp;
    unsigned qf[8][4];
#pragma unroll
    for (int ks = 0; ks < 8; ks++) {
        qf[ks][0] = __float_as_uint(Ps[rA * 68 + ks * 8 + thr]);
        qf[ks][1] = __float_as_uint(Ps[(rA + 8) * 68 + ks * 8 + thr]);
        qf[ks][2] = __float_as_uint(Ps[rA * 68 + ks * 8 + thr + 4]);
        qf[ks][3] = __float_as_uint(Ps[(rA + 8) * 68 + ks * 8 + thr + 4]);
    }

    float o[8][4];
#pragma unroll
    for (int j = 0; j < 8; j++)
#pragma unroll
        for (int c = 0; c < 4; c++) o[j][c] = 0.f;
    float m0 = -INFINITY, m1 = -INFINITY, l0 = 0.f, l1 = 0.f;
    const int r0g = q0 + rA, r1g = r0g + 8;
    const int nt = q0 / 64 + 1;

    for (int kt = 0; kt < nt; kt++) {
        const int kt0 = kt * 64;
        __syncthreads();
#pragma unroll
        for (int j = 0; j < 8; j++) {
            int lin = tid + j * 128;
            int key = lin >> 4, dq = lin & 15;
            size_t g = (size_t)(b * SEQ + kt0 + key) * DMODEL + h * HS + dq * 4;
            float4 kv = *(const float4*)(k + g);
            float4 vv = *(const float4*)(v + g);
            Ks[key * 68 + dq * 4 + 0] = f2tf32(kv.x);
            Ks[key * 68 + dq * 4 + 1] = f2tf32(kv.y);
            Ks[key * 68 + dq * 4 + 2] = f2tf32(kv.z);
            Ks[key * 68 + dq * 4 + 3] = f2tf32(kv.w);
            Vs[key * 72 + dq * 4 + 0] = f2tf32(vv.x);
            Vs[key * 72 + dq * 4 + 1] = f2tf32(vv.y);
            Vs[key * 72 + dq * 4 + 2] = f2tf32(vv.z);
            Vs[key * 72 + dq * 4 + 3] = f2tf32(vv.w);
        }
        __syncthreads();

        float s[8][4];
#pragma unroll
        for (int j = 0; j < 8; j++) { s[j][0] = s[j][1] = s[j][2] = s[j][3] = 0.f; }
#pragma unroll
        for (int j = 0; j < 8; j++) {
#pragma unroll
            for (int ks = 0; ks < 8; ks++) {
                unsigned bf[2];
                bf[0] = __float_as_uint(Ks[(j * 8 + grp) * 68 + ks * 8 + thr]);
                bf[1] = __float_as_uint(Ks[(j * 8 + grp) * 68 + ks * 8 + thr + 4]);
                mma_tf32(s[j], qf[ks], bf);
            }
        }

        if (kt == nt - 1) {
#pragma unroll
            for (int j = 0; j < 8; j++) {
                int c0 = kt0 + j * 8 + 2 * thr;
                s[j][0] = (c0     <= r0g) ? s[j][0] * SCALE : -INFINITY;
                s[j][1] = (c0 + 1 <= r0g) ? s[j][1] * SCALE : -INFINITY;
                s[j][2] = (c0     <= r1g) ? s[j][2] * SCALE : -INFINITY;
                s[j][3] = (c0 + 1 <= r1g) ? s[j][3] * SCALE : -INFINITY;
            }
        } else {
#pragma unroll
            for (int j = 0; j < 8; j++) {
                s[j][0] *= SCALE; s[j][1] *= SCALE;
                s[j][2] *= SCALE; s[j][3] *= SCALE;
            }
        }

        float mx0 = -INFINITY, mx1 = -INFINITY;
#pragma unroll
        for (int j = 0; j < 8; j++) {
            mx0 = fmaxf(mx0, fmaxf(s[j][0], s[j][1]));
            mx1 = fmaxf(mx1, fmaxf(s[j][2], s[j][3]));
        }
        mx0 = fmaxf(mx0, __shfl_xor_sync(0xffffffffu, mx0, 1));
        mx0 = fmaxf(mx0, __shfl_xor_sync(0xffffffffu, mx0, 2));
        mx1 = fmaxf(mx1, __shfl_xor_sync(0xffffffffu, mx1, 1));
        mx1 = fmaxf(mx1, __shfl_xor_sync(0xffffffffu, mx1, 2));
        const float mn0 = fmaxf(m0, mx0), mn1 = fmaxf(m1, mx1);
        const float a0 = __expf(m0 - mn0), a1 = __expf(m1 - mn1);
        m0 = mn0; m1 = mn1;

        float ps0 = 0.f, ps1 = 0.f;
#pragma unroll
        for (int j = 0; j < 8; j++) {
            float p00 = __expf(s[j][0] - mn0);
            float p01 = __expf(s[j][1] - mn0);
            float p10 = __expf(s[j][2] - mn1);
            float p11 = __expf(s[j][3] - mn1);
            ps0 += p00 + p01; ps1 += p10 + p11;
            Ps[rA * 68 + j * 8 + 2 * thr]           = f2tf32(p00);
            Ps[rA * 68 + j * 8 + 2 * thr + 1]       = f2tf32(p01);
            Ps[(rA + 8) * 68 + j * 8 + 2 * thr]     = f2tf32(p10);
            Ps[(rA + 8) * 68 + j * 8 + 2 * thr + 1] = f2tf32(p11);
        }
        ps0 += __shfl_xor_sync(0xffffffffu, ps0, 1);
        ps0 += __shfl_xor_sync(0xffffffffu, ps0, 2);
        ps1 += __shfl_xor_sync(0xffffffffu, ps1, 1);
        ps1 += __shfl_xor_sync(0xffffffffu, ps1, 2);
        l0 = l0 * a0 + ps0;
        l1 = l1 * a1 + ps1;

#pragma unroll
        for (int j = 0; j < 8; j++) {
            o[j][0] *= a0; o[j][1] *= a0;
            o[j][2] *= a1; o[j][3] *= a1;
        }
        __syncwarp();

#pragma unroll
        for (int ks = 0; ks < 8; ks++) {
            unsigned pa[4];
            pa[0] = __float_as_uint(Ps[rA * 68 + ks * 8 + thr]);
            pa[1] = __float_as_uint(Ps[(rA + 8) * 68 + ks * 8 + thr]);
            pa[2] = __float_as_uint(Ps[rA * 68 + ks * 8 + thr + 4]);
            pa[3] = __float_as_uint(Ps[(rA + 8) * 68 + ks * 8 + thr + 4]);
#pragma unroll
            for (int j = 0; j < 8; j++) {
                unsigned vb[2];
                vb[0] = __float_as_uint(Vs[(ks * 8 + thr) * 72 + j * 8 + grp]);
                vb[1] = __float_as_uint(Vs[(ks * 8 + thr + 4) * 72 + j * 8 + grp]);
                mma_tf32(o[j], pa, vb);
            }
        }
    }

    const float i0 = 1.f / l0, i1 = 1.f / l1;
    size_t base0 = (size_t)(b * SEQ + r0g) * DMODEL + h * HS;
    size_t base1 = (size_t)(b * SEQ + r1g) * DMODEL + h * HS;
#pragma unroll
    for (int j = 0; j < 8; j++) {
        int col = j * 8 + 2 * thr;
        *(float2*)(out + base0 + col) = make_float2(o[j][0] * i0, o[j][1] * i0);
        *(float2*)(out + base1 + col) = make_float2(o[j][2] * i1, o[j][3] * i1);
    }
}

// ---------------- fused residual + layernorm (one row per block) ----------------
__global__ void __launch_bounds__(256)
add_ln(const float* __restrict__ x, const float* __restrict__ y,
       const float* __restrict__ g, const float* __restrict__ be,
       float* __restrict__ out)
{
    __shared__ float red[256];
    const int row = blockIdx.x, tid = threadIdx.x;
    const size_t base = (size_t)row * DMODEL;
    float4 xv = ((const float4*)(x + base))[tid];
    float4 yv = ((const float4*)(y + base))[tid];
    float v0 = xv.x + yv.x, v1 = xv.y + yv.y, v2 = xv.z + yv.z, v3 = xv.w + yv.w;

    red[tid] = v0 + v1 + v2 + v3;
    __syncthreads();
    for (int s = 128; s > 0; s >>= 1) {
        if (tid < s) red[tid] += red[tid + s];
        __syncthreads();
    }
    const float mu = red[0] * (1.f / DMODEL);
    __syncthreads();

    float d0 = v0 - mu, d1 = v1 - mu, d2 = v2 - mu, d3 = v3 - mu;
    red[tid] = d0 * d0 + d1 * d1 + d2 * d2 + d3 * d3;
    __syncthreads();
    for (int s = 128; s > 0; s >>= 1) {
        if (tid < s) red[tid] += red[tid + s];
        __syncthreads();
    }
    const float rstd = rsqrtf(red[0] * (1.f / DMODEL) + 1e-5f);

    float4 gv = ((const float4*)g)[tid];
    float4 bv = ((const float4*)be)[tid];
    float4 oo;
    oo.x = d0 * rstd * gv.x + bv.x;
    oo.y = d1 * rstd * gv.y + bv.y;
    oo.z = d2 * rstd * gv.z + bv.z;
    oo.w = d3 * rstd * gv.w + bv.w;
    ((float4*)(out + base))[tid] = oo;
}

// ---------------- host driver ----------------
extern "C" void kernel_launch(void* const* d_in, const int* in_sizes, int n_in,
                              void* d_out, int out_size)
{
    const float* x      = (const float*)d_in[0];
    const float* wq     = (const float*)d_in[1];
    const float* wk     = (const float*)d_in[2];
    const float* wv     = (const float*)d_in[3];
    const float* w_proj = (const float*)d_in[4];
    const float* b_proj = (const float*)d_in[5];
    const float* w1     = (const float*)d_in[6];
    const float* b1     = (const float*)d_in[7];
    const float* w2     = (const float*)d_in[8];
    const float* b2     = (const float*)d_in[9];
    const float* g1     = (const float*)d_in[10];
    const float* be1    = (const float*)d_in[11];
    const float* g2     = (const float*)d_in[12];
    const float* be2    = (const float*)d_in[13];
    float* out = (float*)d_out;

    float *q, *k, *v, *attn, *y, *x1, *hbuf, *y2;
    cudaGetSymbolAddress((void**)&q,    g_q);
    cudaGetSymbolAddress((void**)&k,    g_k);
    cudaGetSymbolAddress((void**)&v,    g_v);
    cudaGetSymbolAddress((void**)&attn, g_attn);
    cudaGetSymbolAddress((void**)&y,    g_y);
    cudaGetSymbolAddress((void**)&x1,   g_x1);
    cudaGetSymbolAddress((void**)&hbuf, g_h);
    cudaGetSymbolAddress((void**)&y2,   g_y2);

    cudaFuncSetAttribute(attn_kernel,
                         cudaFuncAttributeMaxDynamicSharedMemorySize,
                         ATT_SMEM_BYTES);
    cudaFuncSetAttribute(gemm_tf32,
                         cudaFuncAttributeMaxDynamicSharedMemorySize,
                         GEMM_SMEM_BYTES);
    cudaFuncSetAttribute(gemm_qkv,
                         cudaFuncAttributeMaxDynamicSharedMemorySize,
                         GEMM_SMEM_BYTES);

    dim3 blk(128);

    // fused QKV (headmode B indexing) -> [B,S,H*64]
    dim3 gqkv(DMODEL / 128, MTOT / 128, 3);      // (8, 32, 3)
    gemm_qkv<<<gqkv, blk, GEMM_SMEM_BYTES>>>(x, wq, wk, wv, q, k, v);

    // causal attention -> [B,S,H*64]
    dim3 ga(SEQ / 64, NH, BATCH);                // (32, 16, 2)
    attn_kernel<<<ga, dim3(128), ATT_SMEM_BYTES>>>(q, k, v, attn);

    // output projection
    dim3 gq(DMODEL / 128, MTOT / 128);           // (8, 32)
    gemm_tf32<<<gq, blk, GEMM_SMEM_BYTES>>>(attn, w_proj, b_proj, y, DMODEL, DMODEL, DMODEL, DMODEL, 0, 0);

    // x1 = LN(x + y)
    add_ln<<<MTOT, dim3(256)>>>(x, y, g1, be1, x1);

    // MLP
    dim3 gm1(FF / 128, MTOT / 128);              // (32, 32)
    gemm_tf32<<<gm1, blk, GEMM_SMEM_BYTES>>>(x1, w1, b1, hbuf, DMODEL, DMODEL, FF, FF, 1, 0);
    dim3 gm2(DMODEL / 128, MTOT / 128);          // (8, 32)
    gemm_tf32<<<gm2, blk, GEMM_SMEM_BYTES>>>(hbuf, w2, b2, y2, FF, FF, DMODEL, DMODEL, 0, 0);

    // out = LN(x1 + y2)
    add_ln<<<MTOT, dim3(256)>>>(x1, y2, g2, be2, out);
}

// round 8
// speedup vs baseline: 5.7926x; 1.0468x over previous
#include <cuda_runtime.h>
#include <math.h>
#include <stdint.h>

#define SEQ   2048
#define BATCH 2
#define DMODEL 1024
#define NH    16
#define HS    64
#define FF    4096
#define MTOT  (BATCH*SEQ)   /* 4096 rows */

// ---------------- scratch (static device globals; no allocation) ----------------
__device__ float g_q[MTOT*DMODEL];
__device__ float g_k[MTOT*DMODEL];
__device__ float g_v[MTOT*DMODEL];
__device__ float g_attn[MTOT*DMODEL];   // attention out, stored pre-rounded (tf32)
__device__ float g_y[MTOT*DMODEL];
__device__ float g_x1[MTOT*DMODEL];     // full precision (for final LN)
__device__ float g_x1r[MTOT*DMODEL];    // rounded twin (GEMM A operand)
__device__ float g_h[MTOT*FF];          // MLP hidden, stored pre-rounded
__device__ float g_y2[MTOT*DMODEL];
__device__ float g_xr[MTOT*DMODEL];     // rounded x
// pre-rounded weights (same layout as inputs)
__device__ float g_wqr[DMODEL*DMODEL];
__device__ float g_wkr[DMODEL*DMODEL];
__device__ float g_wvr[DMODEL*DMODEL];
__device__ float g_wpr[DMODEL*DMODEL];
__device__ float g_w1r[DMODEL*FF];
__device__ float g_w2r[DMODEL*FF];

__device__ __forceinline__ float f2tf32(float x) {
    unsigned r;
    asm("cvt.rna.tf32.f32 %0, %1;" : "=r"(r) : "f"(x));
    return __uint_as_float(r);
}
__device__ __forceinline__ void mma_tf32(float* c, const unsigned* a, const unsigned* b) {
    asm volatile(
        "mma.sync.aligned.m16n8k8.row.col.f32.tf32.tf32.f32 "
        "{%0,%1,%2,%3},{%4,%5,%6,%7},{%8,%9},{%0,%1,%2,%3};"
        : "+f"(c[0]), "+f"(c[1]), "+f"(c[2]), "+f"(c[3])
        : "r"(a[0]), "r"(a[1]), "r"(a[2]), "r"(a[3]),
          "r"(b[0]), "r"(b[1]));
}
__device__ __forceinline__ void cp16(void* dst, const void* src) {
    unsigned s = (unsigned)__cvta_generic_to_shared(dst);
    asm volatile("cp.async.cg.shared.global [%0], [%1], 16;" :: "r"(s), "l"(src));
}

// ---------------- rna tf32 rounding copy (grid-stride, float4) ------------------
__global__ void __launch_bounds__(256)
round_rna(const float* __restrict__ src, float* __restrict__ dst, int n4)
{
    int i = blockIdx.x * 256 + threadIdx.x;
    int stride = gridDim.x * 256;
    for (; i < n4; i += stride) {
        float4 a = ((const float4*)src)[i];
        float4 t;
        t.x = f2tf32(a.x); t.y = f2tf32(a.y); t.z = f2tf32(a.z); t.w = f2tf32(a.w);
        ((float4*)dst)[i] = t;
    }
}

// ---------------- tf32 GEMM: 128x128 CTA tile, 4 warps x 64x64, kchunk 32 -------
// Both operands PRE-ROUNDED; mainloop = cp.async + plain LDS + HMMA (no cvt).
// headmode: B element (k, n) at B + (n/64)*(K*64) + k*64 + (n%64)
#define AS_FLOATS (128*36)
#define BS_FLOATS (32*136)
#define STG_FLOATS (AS_FLOATS + BS_FLOATS)      /* 8960 */
#define GEMM_SMEM_BYTES (2 * STG_FLOATS * 4)    /* 71680 */

__device__ __forceinline__ void
gemm_core(const float* __restrict__ A, const float* __restrict__ B,
          const float* __restrict__ bias, float* __restrict__ C,
          int K, int lda, int ldb, int ldc, int relu, int headmode, int roundC,
          int m0, int n0, float* sm)
{
    const int tid  = threadIdx.x;
    const int warp = tid >> 5, lane = tid & 31;
    const int wm = warp >> 1, wn = warp & 1;
    const int grp = lane >> 2, thr = lane & 3;
    const int nIter = K >> 5;

    auto prefetch = [&](int it) {
        float* As = sm + (it & 1) * STG_FLOATS;
        float* Bs = As + AS_FLOATS;
        const int k0 = it << 5;
#pragma unroll
        for (int i = 0; i < 8; i++) {
            int idx = tid + i * 128;
            int row = idx >> 3, kq = idx & 7;
            cp16(&As[row * 36 + kq * 4],
                 A + (size_t)(m0 + row) * lda + k0 + kq * 4);
        }
#pragma unroll
        for (int i = 0; i < 8; i++) {
            int idx = tid + i * 128;
            int row = idx >> 5, cq = idx & 31;
            int ncol = n0 + cq * 4;
            const float* bp;
            if (headmode)
                bp = B + (size_t)(ncol >> 6) * ((size_t)K * 64)
                       + (size_t)(k0 + row) * 64 + (ncol & 63);
            else
                bp = B + (size_t)(k0 + row) * ldb + ncol;
            cp16(&Bs[row * 136 + cq * 4], bp);
        }
        asm volatile("cp.async.commit_group;");
    };

    prefetch(0);

    float acc[4][8][4];
#pragma unroll
    for (int i = 0; i < 4; i++)
#pragma unroll
        for (int j = 0; j < 8; j++)
#pragma unroll
            for (int c = 0; c < 4; c++) acc[i][j][c] = 0.f;

    for (int it = 0; it < nIter; ++it) {
        if (it + 1 < nIter) {
            prefetch(it + 1);
            asm volatile("cp.async.wait_group 1;");
        } else {
            asm volatile("cp.async.wait_group 0;");
        }
        __syncthreads();

        const float* As = sm + (it & 1) * STG_FLOATS;
        const float* Bs = As + AS_FLOATS;

#pragma unroll
        for (int ks = 0; ks < 4; ks++) {
            const int kk = ks * 8;
            unsigned a[4][4], b[8][2];
#pragma unroll
            for (int i = 0; i < 4; i++) {
                int rm = wm * 64 + i * 16 + grp;
                a[i][0] = __float_as_uint(As[rm * 36 + kk + thr]);
                a[i][1] = __float_as_uint(As[(rm + 8) * 36 + kk + thr]);
                a[i][2] = __float_as_uint(As[rm * 36 + kk + thr + 4]);
                a[i][3] = __float_as_uint(As[(rm + 8) * 36 + kk + thr + 4]);
            }
#pragma unroll
            for (int j = 0; j < 8; j++) {
                int cn = wn * 64 + j * 8 + grp;
                b[j][0] = __float_as_uint(Bs[(kk + thr) * 136 + cn]);
                b[j][1] = __float_as_uint(Bs[(kk + thr + 4) * 136 + cn]);
            }
#pragma unroll
            for (int i = 0; i < 4; i++)
#pragma unroll
                for (int j = 0; j < 8; j++)
                    mma_tf32(acc[i][j], a[i], b[j]);
        }
        __syncthreads();
    }

#pragma unroll
    for (int i = 0; i < 4; i++) {
        int row = m0 + wm * 64 + i * 16 + grp;
#pragma unroll
        for (int j = 0; j < 8; j++) {
            int col = n0 + wn * 64 + j * 8 + thr * 2;
            float2 r0 = make_float2(acc[i][j][0], acc[i][j][1]);
            float2 r1 = make_float2(acc[i][j][2], acc[i][j][3]);
            if (bias) {
                float2 bv = *(const float2*)(bias + col);
                r0.x += bv.x; r0.y += bv.y;
                r1.x += bv.x; r1.y += bv.y;
            }
            if (relu) {
                r0.x = fmaxf(r0.x, 0.f); r0.y = fmaxf(r0.y, 0.f);
                r1.x = fmaxf(r1.x, 0.f); r1.y = fmaxf(r1.y, 0.f);
            }
            if (roundC) {
                r0.x = f2tf32(r0.x); r0.y = f2tf32(r0.y);
                r1.x = f2tf32(r1.x); r1.y = f2tf32(r1.y);
            }
            *(float2*)(C + (size_t)row * ldc + col) = r0;
            *(float2*)(C + (size_t)(row + 8) * ldc + col) = r1;
        }
    }
}

__global__ void __launch_bounds__(128, 2)
gemm_tf32(const float* __restrict__ A, const float* __restrict__ B,
          const float* __restrict__ bias, float* __restrict__ C,
          int K, int lda, int ldb, int ldc, int relu, int headmode, int roundC)
{
    extern __shared__ float sm[];
    gemm_core(A, B, bias, C, K, lda, ldb, ldc, relu, headmode, roundC,
              blockIdx.y * 128, blockIdx.x * 128, sm);
}

// fused QKV: blockIdx.z selects (weight, output) pair; headmode indexing
__global__ void __launch_bounds__(128, 2)
gemm_qkv(const float* __restrict__ x,
         const float* __restrict__ wq, const float* __restrict__ wk,
         const float* __restrict__ wv,
         float* __restrict__ q, float* __restrict__ k, float* __restrict__ v)
{
    extern __shared__ float sm[];
    const float* B = (blockIdx.z == 0) ? wq : (blockIdx.z == 1) ? wk : wv;
    float*       C = (blockIdx.z == 0) ? q  : (blockIdx.z == 1) ? k  : v;
    gemm_core(x, B, nullptr, C, DMODEL, DMODEL, 0, DMODEL, 0, 1, 0,
              blockIdx.y * 128, blockIdx.x * 128, sm);
}

// ---------------- causal flash attention on tensor cores (tf32 mma) -------------
#define ATT_SMEM_BYTES ((64*68 + 64*72 + 64*68) * 4)

__global__ void __launch_bounds__(128)
attn_kernel(const float* __restrict__ q, const float* __restrict__ k,
            const float* __restrict__ v, float* __restrict__ out)
{
    extern __shared__ float dsm[];
    float* Ks = dsm;
    float* Vs = dsm + 64 * 68;
    float* Ps = dsm + 64 * 68 + 64 * 72;

    const int tid  = threadIdx.x;
    const int warp = tid >> 5, lane = tid & 31;
    const int grp = lane >> 2, thr = lane & 3;
    const int b = blockIdx.z, h = blockIdx.y;
    const int q0 = blockIdx.x * 64;
    const float SCALE = 0.125f;

#pragma unroll
    for (int j = 0; j < 8; j++) {
        int lin = tid + j * 128;
        int row = lin >> 4, dq = lin & 15;
        float4 a = *(const float4*)(q + (size_t)(b * SEQ + q0 + row) * DMODEL + h * HS + dq * 4);
        Ps[row * 68 + dq * 4 + 0] = f2tf32(a.x);
        Ps[row * 68 + dq * 4 + 1] = f2tf32(a.y);
        Ps[row * 68 + dq * 4 + 2] = f2tf32(a.z);
        Ps[row * 68 + dq * 4 + 3] = f2tf32(a.w);
    }
    __syncthreads();

    const int rA = warp * 16 + grp;
    unsigned qf[8][4];
#pragma unroll
    for (int ks = 0; ks < 8; ks++) {
        qf[ks][0] = __float_as_uint(Ps[rA * 68 + ks * 8 + thr]);
        qf[ks][1] = __float_as_uint(Ps[(rA + 8) * 68 + ks * 8 + thr]);
        qf[ks][2] = __float_as_uint(Ps[rA * 68 + ks * 8 + thr + 4]);
        qf[ks][3] = __float_as_uint(Ps[(rA + 8) * 68 + ks * 8 + thr + 4]);
    }

    float o[8][4];
#pragma unroll
    for (int j = 0; j < 8; j++)
#pragma unroll
        for (int c = 0; c < 4; c++) o[j][c] = 0.f;
    float m0 = -INFINITY, m1 = -INFINITY, l0 = 0.f, l1 = 0.f;
    const int r0g = q0 + rA, r1g = r0g + 8;
    const int nt = q0 / 64 + 1;

    for (int kt = 0; kt < nt; kt++) {
        const int kt0 = kt * 64;
        __syncthreads();
#pragma unroll
        for (int j = 0; j < 8; j++) {
            int lin = tid + j * 128;
            int key = lin >> 4, dq = lin & 15;
            size_t g = (size_t)(b * SEQ + kt0 + key) * DMODEL + h * HS + dq * 4;
            float4 kv = *(const float4*)(k + g);
            float4 vv = *(const float4*)(v + g);
            Ks[key * 68 + dq * 4 + 0] = f2tf32(kv.x);
            Ks[key * 68 + dq * 4 + 1] = f2tf32(kv.y);
            Ks[key * 68 + dq * 4 + 2] = f2tf32(kv.z);
            Ks[key * 68 + dq * 4 + 3] = f2tf32(kv.w);
            Vs[key * 72 + dq * 4 + 0] = f2tf32(vv.x);
            Vs[key * 72 + dq * 4 + 1] = f2tf32(vv.y);
            Vs[key * 72 + dq * 4 + 2] = f2tf32(vv.z);
            Vs[key * 72 + dq * 4 + 3] = f2tf32(vv.w);
        }
        __syncthreads();

        float s[8][4];
#pragma unroll
        for (int j = 0; j < 8; j++) { s[j][0] = s[j][1] = s[j][2] = s[j][3] = 0.f; }
#pragma unroll
        for (int j = 0; j < 8; j++) {
#pragma unroll
            for (int ks = 0; ks < 8; ks++) {
                unsigned bf[2];
                bf[0] = __float_as_uint(Ks[(j * 8 + grp) * 68 + ks * 8 + thr]);
                bf[1] = __float_as_uint(Ks[(j * 8 + grp) * 68 + ks * 8 + thr + 4]);
                mma_tf32(s[j], qf[ks], bf);
            }
        }

        if (kt == nt - 1) {
#pragma unroll
            for (int j = 0; j < 8; j++) {
                int c0 = kt0 + j * 8 + 2 * thr;
                s[j][0] = (c0     <= r0g) ? s[j][0] * SCALE : -INFINITY;
                s[j][1] = (c0 + 1 <= r0g) ? s[j][1] * SCALE : -INFINITY;
                s[j][2] = (c0     <= r1g) ? s[j][2] * SCALE : -INFINITY;
                s[j][3] = (c0 + 1 <= r1g) ? s[j][3] * SCALE : -INFINITY;
            }
        } else {
#pragma unroll
            for (int j = 0; j < 8; j++) {
                s[j][0] *= SCALE; s[j][1] *= SCALE;
                s[j][2] *= SCALE; s[j][3] *= SCALE;
            }
        }

        float mx0 = -INFINITY, mx1 = -INFINITY;
#pragma unroll
        for (int j = 0; j < 8; j++) {
            mx0 = fmaxf(mx0, fmaxf(s[j][0], s[j][1]));
            mx1 = fmaxf(mx1, fmaxf(s[j][2], s[j][3]));
        }
        mx0 = fmaxf(mx0, __shfl_xor_sync(0xffffffffu, mx0, 1));
        mx0 = fmaxf(mx0, __shfl_xor_sync(0xffffffffu, mx0, 2));
        mx1 = fmaxf(mx1, __shfl_xor_sync(0xffffffffu, mx1, 1));
        mx1 = fmaxf(mx1, __shfl_xor_sync(0xffffffffu, mx1, 2));
        const float mn0 = fmaxf(m0, mx0), mn1 = fmaxf(m1, mx1);
        const float a0 = __expf(m0 - mn0), a1 = __expf(m1 - mn1);
        m0 = mn0; m1 = mn1;

        float ps0 = 0.f, ps1 = 0.f;
#pragma unroll
        for (int j = 0; j < 8; j++) {
            float p00 = __expf(s[j][0] - mn0);
            float p01 = __expf(s[j][1] - mn0);
            float p10 = __expf(s[j][2] - mn1);
            float p11 = __expf(s[j][3] - mn1);
            ps0 += p00 + p01; ps1 += p10 + p11;
            Ps[rA * 68 + j * 8 + 2 * thr]           = f2tf32(p00);
            Ps[rA * 68 + j * 8 + 2 * thr + 1]       = f2tf32(p01);
            Ps[(rA + 8) * 68 + j * 8 + 2 * thr]     = f2tf32(p10);
            Ps[(rA + 8) * 68 + j * 8 + 2 * thr + 1] = f2tf32(p11);
        }
        ps0 += __shfl_xor_sync(0xffffffffu, ps0, 1);
        ps0 += __shfl_xor_sync(0xffffffffu, ps0, 2);
        ps1 += __shfl_xor_sync(0xffffffffu, ps1, 1);
        ps1 += __shfl_xor_sync(0xffffffffu, ps1, 2);
        l0 = l0 * a0 + ps0;
        l1 = l1 * a1 + ps1;

#pragma unroll
        for (int j = 0; j < 8; j++) {
            o[j][0] *= a0; o[j][1] *= a0;
            o[j][2] *= a1; o[j][3] *= a1;
        }
        __syncwarp();

#pragma unroll
        for (int ks = 0; ks < 8; ks++) {
            unsigned pa[4];
            pa[0] = __float_as_uint(Ps[rA * 68 + ks * 8 + thr]);
            pa[1] = __float_as_uint(Ps[(rA + 8) * 68 + ks * 8 + thr]);
            pa[2] = __float_as_uint(Ps[rA * 68 + ks * 8 + thr + 4]);
            pa[3] = __float_as_uint(Ps[(rA + 8) * 68 + ks * 8 + thr + 4]);
#pragma unroll
            for (int j = 0; j < 8; j++) {
                unsigned vb[2];
                vb[0] = __float_as_uint(Vs[(ks * 8 + thr) * 72 + j * 8 + grp]);
                vb[1] = __float_as_uint(Vs[(ks * 8 + thr + 4) * 72 + j * 8 + grp]);
                mma_tf32(o[j], pa, vb);
            }
        }
    }

    // store output PRE-ROUNDED (feeds proj GEMM A operand directly)
    const float i0 = 1.f / l0, i1 = 1.f / l1;
    size_t base0 = (size_t)(b * SEQ + r0g) * DMODEL + h * HS;
    size_t base1 = (size_t)(b * SEQ + r1g) * DMODEL + h * HS;
#pragma unroll
    for (int j = 0; j < 8; j++) {
        int col = j * 8 + 2 * thr;
        *(float2*)(out + base0 + col) =
            make_float2(f2tf32(o[j][0] * i0), f2tf32(o[j][1] * i0));
        *(float2*)(out + base1 + col) =
            make_float2(f2tf32(o[j][2] * i1), f2tf32(o[j][3] * i1));
    }
}

// ---------------- fused residual + layernorm (one row per block) ----------------
// optional second output: rounded (tf32) copy for GEMM consumption
__global__ void __launch_bounds__(256)
add_ln(const float* __restrict__ x, const float* __restrict__ y,
       const float* __restrict__ g, const float* __restrict__ be,
       float* __restrict__ out, float* __restrict__ out_r)
{
    __shared__ float red[256];
    const int row = blockIdx.x, tid = threadIdx.x;
    const size_t base = (size_t)row * DMODEL;
    float4 xv = ((const float4*)(x + base))[tid];
    float4 yv = ((const float4*)(y + base))[tid];
    float v0 = xv.x + yv.x, v1 = xv.y + yv.y, v2 = xv.z + yv.z, v3 = xv.w + yv.w;

    red[tid] = v0 + v1 + v2 + v3;
    __syncthreads();
    for (int s = 128; s > 0; s >>= 1) {
        if (tid < s) red[tid] += red[tid + s];
        __syncthreads();
    }
    const float mu = red[0] * (1.f / DMODEL);
    __syncthreads();

    float d0 = v0 - mu, d1 = v1 - mu, d2 = v2 - mu, d3 = v3 - mu;
    red[tid] = d0 * d0 + d1 * d1 + d2 * d2 + d3 * d3;
    __syncthreads();
    for (int s = 128; s > 0; s >>= 1) {
        if (tid < s) red[tid] += red[tid + s];
        __syncthreads();
    }
    const float rstd = rsqrtf(red[0] * (1.f / DMODEL) + 1e-5f);

    float4 gv = ((const float4*)g)[tid];
    float4 bv = ((const float4*)be)[tid];
    float4 oo;
    oo.x = d0 * rstd * gv.x + bv.x;
    oo.y = d1 * rstd * gv.y + bv.y;
    oo.z = d2 * rstd * gv.z + bv.z;
    oo.w = d3 * rstd * gv.w + bv.w;
    ((float4*)(out + base))[tid] = oo;
    if (out_r) {
        float4 rr;
        rr.x = f2tf32(oo.x); rr.y = f2tf32(oo.y);
        rr.z = f2tf32(oo.z); rr.w = f2tf32(oo.w);
        ((float4*)(out_r + base))[tid] = rr;
    }
}

// ---------------- host driver ----------------
extern "C" void kernel_launch(void* const* d_in, const int* in_sizes, int n_in,
                              void* d_out, int out_size)
{
    const float* x      = (const float*)d_in[0];
    const float* wq     = (const float*)d_in[1];
    const float* wk     = (const float*)d_in[2];
    const float* wv     = (const float*)d_in[3];
    const float* w_proj = (const float*)d_in[4];
    const float* b_proj = (const float*)d_in[5];
    const float* w1     = (const float*)d_in[6];
    const float* b1     = (const float*)d_in[7];
    const float* w2     = (const float*)d_in[8];
    const float* b2     = (const float*)d_in[9];
    const float* g1     = (const float*)d_in[10];
    const float* be1    = (const float*)d_in[11];
    const float* g2     = (const float*)d_in[12];
    const float* be2    = (const float*)d_in[13];
    float* out = (float*)d_out;

    float *q, *k, *v, *attn, *y, *x1, *x1r, *hbuf, *y2, *xr;
    float *wqr, *wkr, *wvr, *wpr, *w1r, *w2r;
    cudaGetSymbolAddress((void**)&q,    g_q);
    cudaGetSymbolAddress((void**)&k,    g_k);
    cudaGetSymbolAddress((void**)&v,    g_v);
    cudaGetSymbolAddress((void**)&attn, g_attn);
    cudaGetSymbolAddress((void**)&y,    g_y);
    cudaGetSymbolAddress((void**)&x1,   g_x1);
    cudaGetSymbolAddress((void**)&x1r,  g_x1r);
    cudaGetSymbolAddress((void**)&hbuf, g_h);
    cudaGetSymbolAddress((void**)&y2,   g_y2);
    cudaGetSymbolAddress((void**)&xr,   g_xr);
    cudaGetSymbolAddress((void**)&wqr,  g_wqr);
    cudaGetSymbolAddress((void**)&wkr,  g_wkr);
    cudaGetSymbolAddress((void**)&wvr,  g_wvr);
    cudaGetSymbolAddress((void**)&wpr,  g_wpr);
    cudaGetSymbolAddress((void**)&w1r,  g_w1r);
    cudaGetSymbolAddress((void**)&w2r,  g_w2r);

    cudaFuncSetAttribute(attn_kernel,
                         cudaFuncAttributeMaxDynamicSharedMemorySize, ATT_SMEM_BYTES);
    cudaFuncSetAttribute(gemm_tf32,
                         cudaFuncAttributeMaxDynamicSharedMemorySize, GEMM_SMEM_BYTES);
    cudaFuncSetAttribute(gemm_qkv,
                         cudaFuncAttributeMaxDynamicSharedMemorySize, GEMM_SMEM_BYTES);

    // ---- pre-round weights + x (rna tf32, same layout) ----
    {
        const int RB = 592;  // 4 blocks/SM-ish; grid-stride handles any size
        round_rna<<<RB, 256>>>(wq,     wqr, DMODEL*DMODEL/4);
        round_rna<<<RB, 256>>>(wk,     wkr, DMODEL*DMODEL/4);
        round_rna<<<RB, 256>>>(wv,     wvr, DMODEL*DMODEL/4);
        round_rna<<<RB, 256>>>(w_proj, wpr, DMODEL*DMODEL/4);
        round_rna<<<RB, 256>>>(w1,     w1r, DMODEL*FF/4);
        round_rna<<<RB, 256>>>(w2,     w2r, DMODEL*FF/4);
        round_rna<<<RB, 256>>>(x,      xr,  MTOT*DMODEL/4);
    }

    dim3 gb(128);

    // fused QKV (A = rounded x, B = rounded weights) -> [B,S,H*64]
    dim3 gqkv(DMODEL / 128, MTOT / 128, 3);      // (8, 32, 3)
    gemm_qkv<<<gqkv, gb, GEMM_SMEM_BYTES>>>(xr, wqr, wkr, wvr, q, k, v);

    // causal attention -> [B,S,H*64], output pre-rounded
    dim3 ga(SEQ / 64, NH, BATCH);                // (32, 16, 2)
    attn_kernel<<<ga, dim3(128), ATT_SMEM_BYTES>>>(q, k, v, attn);

    // output projection (full-precision C)
    dim3 gq(DMODEL / 128, MTOT / 128);           // (8, 32)
    gemm_tf32<<<gq, gb, GEMM_SMEM_BYTES>>>(attn, wpr, b_proj, y,
                                           DMODEL, DMODEL, DMODEL, DMODEL, 0, 0, 0);

    // x1 = LN(x + y); also write rounded twin
    add_ln<<<MTOT, dim3(256)>>>(x, y, g1, be1, x1, x1r);

    // MLP: hidden stored pre-rounded (relu then round == round then relu)
    dim3 gm1(FF / 128, MTOT / 128);              // (32, 32)
    gemm_tf32<<<gm1, gb, GEMM_SMEM_BYTES>>>(x1r, w1r, b1, hbuf,
                                            DMODEL, DMODEL, FF, FF, 1, 0, 1);
    dim3 gm2(DMODEL / 128, MTOT / 128);          // (8, 32)
    gemm_tf32<<<gm2, gb, GEMM_SMEM_BYTES>>>(hbuf, w2r, b2, y2,
                                            FF, FF, DMODEL, DMODEL, 0, 0, 0);

    // out = LN(x1 + y2)
    add_ln<<<MTOT, dim3(256)>>>(x1, y2, g2, be2, out, nullptr);
}

// round 9
// speedup vs baseline: 8.6961x; 1.5013x over previous
#include <cuda_runtime.h>
#include <cuda_fp16.h>
#include <math.h>
#include <stdint.h>

#define SEQ   2048
#define BATCH 2
#define DMODEL 1024
#define NH    16
#define HS    64
#define FF    4096
#define MTOT  (BATCH*SEQ)   /* 4096 rows */

// ---------------- scratch (static device globals; no allocation) ----------------
__device__ float  g_q[MTOT*DMODEL];
__device__ float  g_k[MTOT*DMODEL];
__device__ float  g_v[MTOT*DMODEL];
__device__ __half g_attn[MTOT*DMODEL];   // attention out (half, feeds proj GEMM)
__device__ float  g_y[MTOT*DMODEL];
__device__ float  g_x1[MTOT*DMODEL];     // full precision (for final LN)
__device__ __half g_x1h[MTOT*DMODEL];    // half twin (GEMM A operand)
__device__ __half g_h[MTOT*FF];          // MLP hidden (half)
__device__ float  g_y2[MTOT*DMODEL];
__device__ __half g_xh[MTOT*DMODEL];     // half x
// transposed half weights, layout [N][K] (K contiguous)
__device__ __half g_wqh[DMODEL*DMODEL];
__device__ __half g_wkh[DMODEL*DMODEL];
__device__ __half g_wvh[DMODEL*DMODEL];
__device__ __half g_wph[DMODEL*DMODEL];
__device__ __half g_w1h[(size_t)FF*DMODEL];
__device__ __half g_w2h[(size_t)DMODEL*FF];

__device__ __forceinline__ float f2tf32(float x) {
    unsigned r;
    asm("cvt.rna.tf32.f32 %0, %1;" : "=r"(r) : "f"(x));
    return __uint_as_float(r);
}
__device__ __forceinline__ void mma_tf32(float* c, const unsigned* a, const unsigned* b) {
    asm volatile(
        "mma.sync.aligned.m16n8k8.row.col.f32.tf32.tf32.f32 "
        "{%0,%1,%2,%3},{%4,%5,%6,%7},{%8,%9},{%0,%1,%2,%3};"
        : "+f"(c[0]), "+f"(c[1]), "+f"(c[2]), "+f"(c[3])
        : "r"(a[0]), "r"(a[1]), "r"(a[2]), "r"(a[3]),
          "r"(b[0]), "r"(b[1]));
}
__device__ __forceinline__ void mma_f16(float* c, const unsigned* a, const unsigned* b) {
    asm volatile(
        "mma.sync.aligned.m16n8k16.row.col.f32.f16.f16.f32 "
        "{%0,%1,%2,%3},{%4,%5,%6,%7},{%8,%9},{%0,%1,%2,%3};"
        : "+f"(c[0]), "+f"(c[1]), "+f"(c[2]), "+f"(c[3])
        : "r"(a[0]), "r"(a[1]), "r"(a[2]), "r"(a[3]),
          "r"(b[0]), "r"(b[1]));
}
__device__ __forceinline__ void cp16(void* dst, const void* src) {
    unsigned s = (unsigned)__cvta_generic_to_shared(dst);
    asm volatile("cp.async.cg.shared.global [%0], [%1], 16;" :: "r"(s), "l"(src));
}

// ---------------- pre-pass kernels ----------------------------------------------
// fp32 -> half copy (grid-stride, float4 granularity)
__global__ void __launch_bounds__(256)
round_h(const float* __restrict__ src, __half* __restrict__ dst, int n4)
{
    int i = blockIdx.x * 256 + threadIdx.x;
    int stride = gridDim.x * 256;
    for (; i < n4; i += stride) {
        float4 a = ((const float4*)src)[i];
        __half2 h0 = __floats2half2_rn(a.x, a.y);
        __half2 h1 = __floats2half2_rn(a.z, a.w);
        ((__half2*)dst)[2 * i]     = h0;
        ((__half2*)dst)[2 * i + 1] = h1;
    }
}

// W[K][N] fp32 -> Wt[N][K] half; blockIdx.z = matrix slab (head), stride K*N
__global__ void __launch_bounds__(256)
transpose_h(const float* __restrict__ W, __half* __restrict__ Wt, int K, int N)
{
    __shared__ float t[32][33];
    const size_t bo = (size_t)blockIdx.z * K * N;
    const int n0 = blockIdx.x * 32, k0 = blockIdx.y * 32;
    const int tx = threadIdx.x & 31, ty = threadIdx.x >> 5;   // ty 0..7
#pragma unroll
    for (int i = 0; i < 4; i++)
        t[ty + i * 8][tx] = W[bo + (size_t)(k0 + ty + i * 8) * N + n0 + tx];
    __syncthreads();
#pragma unroll
    for (int i = 0; i < 4; i++)
        Wt[bo + (size_t)(n0 + ty + i * 8) * K + k0 + tx] =
            __float2half(t[tx][ty + i * 8]);
}

// ---------------- fp16 GEMM: 128x128 CTA tile, 4 warps x 64x64, kchunk 64 -------
// A [M][K] half row-major; B [N][K] half (K contiguous). mma m16n8k16 f16->f32.
// smem rows padded 128B->144B (fragment LDS provably conflict-free).
#define ROWB 144
#define TILE_BYTES (128*ROWB)        /* 18432 */
#define STG_BYTES  (2*TILE_BYTES)    /* 36864 */
#define GEMM_SMEM_BYTES (2*STG_BYTES) /* 73728 */

__device__ __forceinline__ void
gemm_core_h(const __half* __restrict__ A, const __half* __restrict__ B,
            const float* __restrict__ bias, void* __restrict__ Cv,
            int K, int ldc, int relu, int halfC, int m0, int n0, char* sm)
{
    const int tid  = threadIdx.x;
    const int warp = tid >> 5, lane = tid & 31;
    const int wm = warp >> 1, wn = warp & 1;
    const int grp = lane >> 2, thr = lane & 3;
    const int nIter = K >> 6;

    auto prefetch = [&](int it) {
        char* As = sm + (it & 1) * STG_BYTES;
        char* Bs = As + TILE_BYTES;
        const int k0 = it << 6;
#pragma unroll
        for (int i = 0; i < 8; i++) {
            int idx = tid + i * 128;
            int row = idx >> 3, c = idx & 7;
            cp16(As + row * ROWB + c * 16,
                 A + (size_t)(m0 + row) * K + k0 + c * 8);
        }
#pragma unroll
        for (int i = 0; i < 8; i++) {
            int idx = tid + i * 128;
            int row = idx >> 3, c = idx & 7;
            cp16(Bs + row * ROWB + c * 16,
                 B + (size_t)(n0 + row) * K + k0 + c * 8);
        }
        asm volatile("cp.async.commit_group;");
    };

    prefetch(0);

    float acc[4][8][4];
#pragma unroll
    for (int i = 0; i < 4; i++)
#pragma unroll
        for (int j = 0; j < 8; j++)
#pragma unroll
            for (int c = 0; c < 4; c++) acc[i][j][c] = 0.f;

    for (int it = 0; it < nIter; ++it) {
        if (it + 1 < nIter) {
            prefetch(it + 1);
            asm volatile("cp.async.wait_group 1;");
        } else {
            asm volatile("cp.async.wait_group 0;");
        }
        __syncthreads();

        const char* As = sm + (it & 1) * STG_BYTES;
        const char* Bs = As + TILE_BYTES;

#pragma unroll
        for (int ks = 0; ks < 4; ks++) {
            unsigned a[4][4], b[8][2];
#pragma unroll
            for (int i = 0; i < 4; i++) {
                const char* pa = As + (wm * 64 + i * 16 + grp) * ROWB + ks * 32 + thr * 4;
                a[i][0] = *(const unsigned*)pa;                  // row g,   k 2t..2t+1
                a[i][1] = *(const unsigned*)(pa + 8 * ROWB);     // row g+8
                a[i][2] = *(const unsigned*)(pa + 16);           // row g,   k 2t+8..
                a[i][3] = *(const unsigned*)(pa + 8 * ROWB + 16);
            }
#pragma unroll
            for (int j = 0; j < 8; j++) {
                const char* pb = Bs + (wn * 64 + j * 8 + grp) * ROWB + ks * 32 + thr * 4;
                b[j][0] = *(const unsigned*)pb;                  // n g, k 2t..2t+1
                b[j][1] = *(const unsigned*)(pb + 16);           // n g, k 2t+8..
            }
#pragma unroll
            for (int i = 0; i < 4; i++)
#pragma unroll
                for (int j = 0; j < 8; j++)
                    mma_f16(acc[i][j], a[i], b[j]);
        }
        __syncthreads();
    }

#pragma unroll
    for (int i = 0; i < 4; i++) {
        int row = m0 + wm * 64 + i * 16 + grp;
#pragma unroll
        for (int j = 0; j < 8; j++) {
            int col = n0 + wn * 64 + j * 8 + thr * 2;
            float v00 = acc[i][j][0], v01 = acc[i][j][1];
            float v10 = acc[i][j][2], v11 = acc[i][j][3];
            if (bias) {
                float2 bv = *(const float2*)(bias + col);
                v00 += bv.x; v01 += bv.y; v10 += bv.x; v11 += bv.y;
            }
            if (relu) {
                v00 = fmaxf(v00, 0.f); v01 = fmaxf(v01, 0.f);
                v10 = fmaxf(v10, 0.f); v11 = fmaxf(v11, 0.f);
            }
            if (halfC) {
                __half* C = (__half*)Cv;
                *(__half2*)(C + (size_t)row * ldc + col)       = __floats2half2_rn(v00, v01);
                *(__half2*)(C + (size_t)(row + 8) * ldc + col) = __floats2half2_rn(v10, v11);
            } else {
                float* C = (float*)Cv;
                *(float2*)(C + (size_t)row * ldc + col)       = make_float2(v00, v01);
                *(float2*)(C + (size_t)(row + 8) * ldc + col) = make_float2(v10, v11);
            }
        }
    }
}

__global__ void __launch_bounds__(128, 2)
gemm_h(const __half* __restrict__ A, const __half* __restrict__ B,
       const float* __restrict__ bias, void* __restrict__ C,
       int K, int ldc, int relu, int halfC)
{
    extern __shared__ char sm[];
    gemm_core_h(A, B, bias, C, K, ldc, relu, halfC,
                blockIdx.y * 128, blockIdx.x * 128, sm);
}

// fused QKV: blockIdx.z selects (weight, output) pair; outputs fp32 for attention
__global__ void __launch_bounds__(128, 2)
gemm_qkv_h(const __half* __restrict__ xh,
           const __half* __restrict__ wqh, const __half* __restrict__ wkh,
           const __half* __restrict__ wvh,
           float* __restrict__ q, float* __restrict__ k, float* __restrict__ v)
{
    extern __shared__ char sm[];
    const __half* B = (blockIdx.z == 0) ? wqh : (blockIdx.z == 1) ? wkh : wvh;
    float*        C = (blockIdx.z == 0) ? q   : (blockIdx.z == 1) ? k   : v;
    gemm_core_h(xh, B, nullptr, C, DMODEL, DMODEL, 0, 0,
                blockIdx.y * 128, blockIdx.x * 128, sm);
}

// ---------------- causal flash attention on tensor cores (tf32 mma) -------------
#define ATT_SMEM_BYTES ((64*68 + 64*72 + 64*68) * 4)

__global__ void __launch_bounds__(128)
attn_kernel(const float* __restrict__ q, const float* __restrict__ k,
            const float* __restrict__ v, __half* __restrict__ out)
{
    extern __shared__ float dsm[];
    float* Ks = dsm;
    float* Vs = dsm + 64 * 68;
    float* Ps = dsm + 64 * 68 + 64 * 72;

    const int tid  = threadIdx.x;
    const int warp = tid >> 5, lane = tid & 31;
    const int grp = lane >> 2, thr = lane & 3;
    const int b = blockIdx.z, h = blockIdx.y;
    const int q0 = blockIdx.x * 64;
    const float SCALE = 0.125f;

#pragma unroll
    for (int j = 0; j < 8; j++) {
        int lin = tid + j * 128;
        int row = lin >> 4, dq = lin & 15;
        float4 a = *(const float4*)(q + (size_t)(b * SEQ + q0 + row) * DMODEL + h * HS + dq * 4);
        Ps[row * 68 + dq * 4 + 0] = f2tf32(a.x);
        Ps[row * 68 + dq * 4 + 1] = f2tf32(a.y);
        Ps[row * 68 + dq * 4 + 2] = f2tf32(a.z);
        Ps[row * 68 + dq * 4 + 3] = f2tf32(a.w);
    }
    __syncthreads();

    const int rA = warp * 16 + grp;
    unsigned qf[8][4];
#pragma unroll
    for (int ks = 0; ks < 8; ks++) {
        qf[ks][0] = __float_as_uint(Ps[rA * 68 + ks * 8 + thr]);
        qf[ks][1] = __float_as_uint(Ps[(rA + 8) * 68 + ks * 8 + thr]);
        qf[ks][2] = __float_as_uint(Ps[rA * 68 + ks * 8 + thr + 4]);
        qf[ks][3] = __float_as_uint(Ps[(rA + 8) * 68 + ks * 8 + thr + 4]);
    }

    float o[8][4];
#pragma unroll
    for (int j = 0; j < 8; j++)
#pragma unroll
        for (int c = 0; c < 4; c++) o[j][c] = 0.f;
    float m0 = -INFINITY, m1 = -INFINITY, l0 = 0.f, l1 = 0.f;
    const int r0g = q0 + rA, r1g = r0g + 8;
    const int nt = q0 / 64 + 1;

    for (int kt = 0; kt < nt; kt++) {
        const int kt0 = kt * 64;
        __syncthreads();
#pragma unroll
        for (int j = 0; j < 8; j++) {
            int lin = tid + j * 128;
            int key = lin >> 4, dq = lin & 15;
            size_t g = (size_t)(b * SEQ + kt0 + key) * DMODEL + h * HS + dq * 4;
            float4 kv = *(const float4*)(k + g);
            float4 vv = *(const float4*)(v + g);
            Ks[key * 68 + dq * 4 + 0] = f2tf32(kv.x);
            Ks[key * 68 + dq * 4 + 1] = f2tf32(kv.y);
            Ks[key * 68 + dq * 4 + 2] = f2tf32(kv.z);
            Ks[key * 68 + dq * 4 + 3] = f2tf32(kv.w);
            Vs[key * 72 + dq * 4 + 0] = f2tf32(vv.x);
            Vs[key * 72 + dq * 4 + 1] = f2tf32(vv.y);
            Vs[key * 72 + dq * 4 + 2] = f2tf32(vv.z);
            Vs[key * 72 + dq * 4 + 3] = f2tf32(vv.w);
        }
        __syncthreads();

        float s[8][4];
#pragma unroll
        for (int j = 0; j < 8; j++) { s[j][0] = s[j][1] = s[j][2] = s[j][3] = 0.f; }
#pragma unroll
        for (int j = 0; j < 8; j++) {
#pragma unroll
            for (int ks = 0; ks < 8; ks++) {
                unsigned bf[2];
                bf[0] = __float_as_uint(Ks[(j * 8 + grp) * 68 + ks * 8 + thr]);
                bf[1] = __float_as_uint(Ks[(j * 8 + grp) * 68 + ks * 8 + thr + 4]);
                mma_tf32(s[j], qf[ks], bf);
            }
        }

        if (kt == nt - 1) {
#pragma unroll
            for (int j = 0; j < 8; j++) {
                int c0 = kt0 + j * 8 + 2 * thr;
                s[j][0] = (c0     <= r0g) ? s[j][0] * SCALE : -INFINITY;
                s[j][1] = (c0 + 1 <= r0g) ? s[j][1] * SCALE : -INFINITY;
                s[j][2] = (c0     <= r1g) ? s[j][2] * SCALE : -INFINITY;
                s[j][3] = (c0 + 1 <= r1g) ? s[j][3] * SCALE : -INFINITY;
            }
        } else {
#pragma unroll
            for (int j = 0; j < 8; j++) {
                s[j][0] *= SCALE; s[j][1] *= SCALE;
                s[j][2] *= SCALE; s[j][3] *= SCALE;
            }
        }

        float mx0 = -INFINITY, mx1 = -INFINITY;
#pragma unroll
        for (int j = 0; j < 8; j++) {
            mx0 = fmaxf(mx0, fmaxf(s[j][0], s[j][1]));
            mx1 = fmaxf(mx1, fmaxf(s[j][2], s[j][3]));
        }
        mx0 = fmaxf(mx0, __shfl_xor_sync(0xffffffffu, mx0, 1));
        mx0 = fmaxf(mx0, __shfl_xor_sync(0xffffffffu, mx0, 2));
        mx1 = fmaxf(mx1, __shfl_xor_sync(0xffffffffu, mx1, 1));
        mx1 = fmaxf(mx1, __shfl_xor_sync(0xffffffffu, mx1, 2));
        const float mn0 = fmaxf(m0, mx0), mn1 = fmaxf(m1, mx1);
        const float a0 = __expf(m0 - mn0), a1 = __expf(m1 - mn1);
        m0 = mn0; m1 = mn1;

        float ps0 = 0.f, ps1 = 0.f;
#pragma unroll
        for (int j = 0; j < 8; j++) {
            float p00 = __expf(s[j][0] - mn0);
            float p01 = __expf(s[j][1] - mn0);
            float p10 = __expf(s[j][2] - mn1);
            float p11 = __expf(s[j][3] - mn1);
            ps0 += p00 + p01; ps1 += p10 + p11;
            Ps[rA * 68 + j * 8 + 2 * thr]           = f2tf32(p00);
            Ps[rA * 68 + j * 8 + 2 * thr + 1]       = f2tf32(p01);
            Ps[(rA + 8) * 68 + j * 8 + 2 * thr]     = f2tf32(p10);
            Ps[(rA + 8) * 68 + j * 8 + 2 * thr + 1] = f2tf32(p11);
        }
        ps0 += __shfl_xor_sync(0xffffffffu, ps0, 1);
        ps0 += __shfl_xor_sync(0xffffffffu, ps0, 2);
        ps1 += __shfl_xor_sync(0xffffffffu, ps1, 1);
        ps1 += __shfl_xor_sync(0xffffffffu, ps1, 2);
        l0 = l0 * a0 + ps0;
        l1 = l1 * a1 + ps1;

#pragma unroll
        for (int j = 0; j < 8; j++) {
            o[j][0] *= a0; o[j][1] *= a0;
            o[j][2] *= a1; o[j][3] *= a1;
        }
        __syncwarp();

#pragma unroll
        for (int ks = 0; ks < 8; ks++) {
            unsigned pa[4];
            pa[0] = __float_as_uint(Ps[rA * 68 + ks * 8 + thr]);
            pa[1] = __float_as_uint(Ps[(rA + 8) * 68 + ks * 8 + thr]);
            pa[2] = __float_as_uint(Ps[rA * 68 + ks * 8 + thr + 4]);
            pa[3] = __float_as_uint(Ps[(rA + 8) * 68 + ks * 8 + thr + 4]);
#pragma unroll
            for (int j = 0; j < 8; j++) {
                unsigned vb[2];
                vb[0] = __float_as_uint(Vs[(ks * 8 + thr) * 72 + j * 8 + grp]);
                vb[1] = __float_as_uint(Vs[(ks * 8 + thr + 4) * 72 + j * 8 + grp]);
                mma_tf32(o[j], pa, vb);
            }
        }
    }

    // store output as HALF (feeds proj GEMM A operand)
    const float i0 = 1.f / l0, i1 = 1.f / l1;
    size_t base0 = (size_t)(b * SEQ + r0g) * DMODEL + h * HS;
    size_t base1 = (size_t)(b * SEQ + r1g) * DMODEL + h * HS;
#pragma unroll
    for (int j = 0; j < 8; j++) {
        int col = j * 8 + 2 * thr;
        *(__half2*)(out + base0 + col) = __floats2half2_rn(o[j][0] * i0, o[j][1] * i0);
        *(__half2*)(out + base1 + col) = __floats2half2_rn(o[j][2] * i1, o[j][3] * i1);
    }
}

// ---------------- fused residual + layernorm (one row per block) ----------------
__global__ void __launch_bounds__(256)
add_ln(const float* __restrict__ x, const float* __restrict__ y,
       const float* __restrict__ g, const float* __restrict__ be,
       float* __restrict__ out, __half* __restrict__ out_h)
{
    __shared__ float red[256];
    const int row = blockIdx.x, tid = threadIdx.x;
    const size_t base = (size_t)row * DMODEL;
    float4 xv = ((const float4*)(x + base))[tid];
    float4 yv = ((const float4*)(y + base))[tid];
    float v0 = xv.x + yv.x, v1 = xv.y + yv.y, v2 = xv.z + yv.z, v3 = xv.w + yv.w;

    red[tid] = v0 + v1 + v2 + v3;
    __syncthreads();
    for (int s = 128; s > 0; s >>= 1) {
        if (tid < s) red[tid] += red[tid + s];
        __syncthreads();
    }
    const float mu = red[0] * (1.f / DMODEL);
    __syncthreads();

    float d0 = v0 - mu, d1 = v1 - mu, d2 = v2 - mu, d3 = v3 - mu;
    red[tid] = d0 * d0 + d1 * d1 + d2 * d2 + d3 * d3;
    __syncthreads();
    for (int s = 128; s > 0; s >>= 1) {
        if (tid < s) red[tid] += red[tid + s];
        __syncthreads();
    }
    const float rstd = rsqrtf(red[0] * (1.f / DMODEL) + 1e-5f);

    float4 gv = ((const float4*)g)[tid];
    float4 bv = ((const float4*)be)[tid];
    float4 oo;
    oo.x = d0 * rstd * gv.x + bv.x;
    oo.y = d1 * rstd * gv.y + bv.y;
    oo.z = d2 * rstd * gv.z + bv.z;
    oo.w = d3 * rstd * gv.w + bv.w;
    ((float4*)(out + base))[tid] = oo;
    if (out_h) {
        *(__half2*)(out_h + base + tid * 4)     = __floats2half2_rn(oo.x, oo.y);
        *(__half2*)(out_h + base + tid * 4 + 2) = __floats2half2_rn(oo.z, oo.w);
    }
}

// ---------------- host driver ----------------
extern "C" void kernel_launch(void* const* d_in, const int* in_sizes, int n_in,
                              void* d_out, int out_size)
{
    const float* x      = (const float*)d_in[0];
    const float* wq     = (const float*)d_in[1];
    const float* wk     = (const float*)d_in[2];
    const float* wv     = (const float*)d_in[3];
    const float* w_proj = (const float*)d_in[4];
    const float* b_proj = (const float*)d_in[5];
    const float* w1     = (const float*)d_in[6];
    const float* b1     = (const float*)d_in[7];
    const float* w2     = (const float*)d_in[8];
    const float* b2     = (const float*)d_in[9];
    const float* g1     = (const float*)d_in[10];
    const float* be1    = (const float*)d_in[11];
    const float* g2     = (const float*)d_in[12];
    const float* be2    = (const float*)d_in[13];
    float* out = (float*)d_out;

    float *q, *k, *v, *y, *x1, *y2;
    __half *attn, *x1h, *hbuf, *xh;
    __half *wqh, *wkh, *wvh, *wph, *w1h, *w2h;
    cudaGetSymbolAddress((void**)&q,    g_q);
    cudaGetSymbolAddress((void**)&k,    g_k);
    cudaGetSymbolAddress((void**)&v,    g_v);
    cudaGetSymbolAddress((void**)&attn, g_attn);
    cudaGetSymbolAddress((void**)&y,    g_y);
    cudaGetSymbolAddress((void**)&x1,   g_x1);
    cudaGetSymbolAddress((void**)&x1h,  g_x1h);
    cudaGetSymbolAddress((void**)&hbuf, g_h);
    cudaGetSymbolAddress((void**)&y2,   g_y2);
    cudaGetSymbolAddress((void**)&xh,   g_xh);
    cudaGetSymbolAddress((void**)&wqh,  g_wqh);
    cudaGetSymbolAddress((void**)&wkh,  g_wkh);
    cudaGetSymbolAddress((void**)&wvh,  g_wvh);
    cudaGetSymbolAddress((void**)&wph,  g_wph);
    cudaGetSymbolAddress((void**)&w1h,  g_w1h);
    cudaGetSymbolAddress((void**)&w2h,  g_w2h);

    cudaFuncSetAttribute(attn_kernel,
                         cudaFuncAttributeMaxDynamicSharedMemorySize, ATT_SMEM_BYTES);
    cudaFuncSetAttribute(gemm_h,
                         cudaFuncAttributeMaxDynamicSharedMemorySize, GEMM_SMEM_BYTES);
    cudaFuncSetAttribute(gemm_qkv_h,
                         cudaFuncAttributeMaxDynamicSharedMemorySize, GEMM_SMEM_BYTES);

    dim3 tb(256);

    // ---- pre-pass: transpose+convert weights to half [N][K]; convert x ----
    // per-head QKV weights: [NH][K=1024][64] -> [NH][64][1024] == [n][k], n=h*64+c
    transpose_h<<<dim3(HS/32, DMODEL/32, NH), tb>>>(wq, wqh, DMODEL, HS);
    transpose_h<<<dim3(HS/32, DMODEL/32, NH), tb>>>(wk, wkh, DMODEL, HS);
    transpose_h<<<dim3(HS/32, DMODEL/32, NH), tb>>>(wv, wvh, DMODEL, HS);
    transpose_h<<<dim3(DMODEL/32, DMODEL/32, 1), tb>>>(w_proj, wph, DMODEL, DMODEL);
    transpose_h<<<dim3(FF/32, DMODEL/32, 1), tb>>>(w1, w1h, DMODEL, FF);
    transpose_h<<<dim3(DMODEL/32, FF/32, 1), tb>>>(w2, w2h, FF, DMODEL);
    round_h<<<592, 256>>>(x, xh, MTOT*DMODEL/4);

    dim3 gb(128);

    // fused QKV -> fp32 q,k,v in [B,S,H*64]
    dim3 gqkv(DMODEL / 128, MTOT / 128, 3);      // (8, 32, 3)
    gemm_qkv_h<<<gqkv, gb, GEMM_SMEM_BYTES>>>(xh, wqh, wkh, wvh, q, k, v);

    // causal attention -> half attn
    dim3 ga(SEQ / 64, NH, BATCH);                // (32, 16, 2)
    attn_kernel<<<ga, dim3(128), ATT_SMEM_BYTES>>>(q, k, v, attn);

    // output projection (fp32 C)
    dim3 gq(DMODEL / 128, MTOT / 128);           // (8, 32)
    gemm_h<<<gq, gb, GEMM_SMEM_BYTES>>>(attn, wph, b_proj, y, DMODEL, DMODEL, 0, 0);

    // x1 = LN(x + y); also half twin
    add_ln<<<MTOT, tb>>>(x, y, g1, be1, x1, x1h);

    // MLP
    dim3 gm1(FF / 128, MTOT / 128);              // (32, 32)
    gemm_h<<<gm1, gb, GEMM_SMEM_BYTES>>>(x1h, w1h, b1, hbuf, DMODEL, FF, 1, 1);
    dim3 gm2(DMODEL / 128, MTOT / 128);          // (8, 32)
    gemm_h<<<gm2, gb, GEMM_SMEM_BYTES>>>(hbuf, w2h, b2, y2, FF, DMODEL, 0, 0);

    // out = LN(x1 + y2)
    add_ln<<<MTOT, tb>>>(x1, y2, g2, be2, out, nullptr);
}

// round 10
// speedup vs baseline: 10.4634x; 1.2032x over previous
#include <cuda_runtime.h>
#include <cuda_fp16.h>
#include <math.h>
#include <stdint.h>

#define SEQ   2048
#define BATCH 2
#define DMODEL 1024
#define NH    16
#define HS    64
#define FF    4096
#define MTOT  (BATCH*SEQ)   /* 4096 rows */

// ---------------- scratch (static device globals; no allocation) ----------------
__device__ __half g_q[MTOT*DMODEL];
__device__ __half g_k[MTOT*DMODEL];
__device__ __half g_v[MTOT*DMODEL];
__device__ __half g_attn[MTOT*DMODEL];   // attention out (half, feeds proj GEMM)
__device__ float  g_y[MTOT*DMODEL];
__device__ float  g_x1[MTOT*DMODEL];     // full precision (for final LN)
__device__ __half g_x1h[MTOT*DMODEL];    // half twin (GEMM A operand)
__device__ __half g_h[MTOT*FF];          // MLP hidden (half)
__device__ float  g_y2[MTOT*DMODEL];
__device__ __half g_xh[MTOT*DMODEL];     // half x
// transposed half weights, layout [N][K] (K contiguous)
__device__ __half g_wqh[DMODEL*DMODEL];
__device__ __half g_wkh[DMODEL*DMODEL];
__device__ __half g_wvh[DMODEL*DMODEL];
__device__ __half g_wph[DMODEL*DMODEL];
__device__ __half g_w1h[(size_t)FF*DMODEL];
__device__ __half g_w2h[(size_t)DMODEL*FF];

__device__ __forceinline__ void mma_f16(float* c, const unsigned* a, const unsigned* b) {
    asm volatile(
        "mma.sync.aligned.m16n8k16.row.col.f32.f16.f16.f32 "
        "{%0,%1,%2,%3},{%4,%5,%6,%7},{%8,%9},{%0,%1,%2,%3};"
        : "+f"(c[0]), "+f"(c[1]), "+f"(c[2]), "+f"(c[3])
        : "r"(a[0]), "r"(a[1]), "r"(a[2]), "r"(a[3]),
          "r"(b[0]), "r"(b[1]));
}
__device__ __forceinline__ void cp16(void* dst, const void* src) {
    unsigned s = (unsigned)__cvta_generic_to_shared(dst);
    asm volatile("cp.async.cg.shared.global [%0], [%1], 16;" :: "r"(s), "l"(src));
}
__device__ __forceinline__ uint32_t s2u(const void* p) {
    return (uint32_t)__cvta_generic_to_shared(p);
}
__device__ __forceinline__ void ldmx4t(unsigned* r, uint32_t addr) {
    asm volatile(
        "ldmatrix.sync.aligned.m8n8.x4.trans.shared.b16 {%0,%1,%2,%3}, [%4];"
        : "=r"(r[0]), "=r"(r[1]), "=r"(r[2]), "=r"(r[3]) : "r"(addr));
}

// ---------------- pre-pass kernels ----------------------------------------------
__global__ void __launch_bounds__(256)
round_h(const float* __restrict__ src, __half* __restrict__ dst, int n4)
{
    int i = blockIdx.x * 256 + threadIdx.x;
    int stride = gridDim.x * 256;
    for (; i < n4; i += stride) {
        float4 a = ((const float4*)src)[i];
        ((__half2*)dst)[2 * i]     = __floats2half2_rn(a.x, a.y);
        ((__half2*)dst)[2 * i + 1] = __floats2half2_rn(a.z, a.w);
    }
}

// W[K][N] fp32 -> Wt[N][K] half; blockIdx.z = matrix slab (head), stride K*N
__global__ void __launch_bounds__(256)
transpose_h(const float* __restrict__ W, __half* __restrict__ Wt, int K, int N)
{
    __shared__ float t[32][33];
    const size_t bo = (size_t)blockIdx.z * K * N;
    const int n0 = blockIdx.x * 32, k0 = blockIdx.y * 32;
    const int tx = threadIdx.x & 31, ty = threadIdx.x >> 5;
#pragma unroll
    for (int i = 0; i < 4; i++)
        t[ty + i * 8][tx] = W[bo + (size_t)(k0 + ty + i * 8) * N + n0 + tx];
    __syncthreads();
#pragma unroll
    for (int i = 0; i < 4; i++)
        Wt[bo + (size_t)(n0 + ty + i * 8) * K + k0 + tx] =
            __float2half(t[tx][ty + i * 8]);
}

// ---------------- fp16 GEMM: 128x128 CTA tile, 4 warps x 64x64, kchunk 64 -------
#define ROWB 144
#define TILE_BYTES (128*ROWB)
#define STG_BYTES  (2*TILE_BYTES)
#define GEMM_SMEM_BYTES (2*STG_BYTES) /* 73728 */

__device__ __forceinline__ void
gemm_core_h(const __half* __restrict__ A, const __half* __restrict__ B,
            const float* __restrict__ bias, void* __restrict__ Cv,
            int K, int ldc, int relu, int halfC, int m0, int n0, char* sm)
{
    const int tid  = threadIdx.x;
    const int warp = tid >> 5, lane = tid & 31;
    const int wm = warp >> 1, wn = warp & 1;
    const int grp = lane >> 2, thr = lane & 3;
    const int nIter = K >> 6;

    auto prefetch = [&](int it) {
        char* As = sm + (it & 1) * STG_BYTES;
        char* Bs = As + TILE_BYTES;
        const int k0 = it << 6;
#pragma unroll
        for (int i = 0; i < 8; i++) {
            int idx = tid + i * 128;
            int row = idx >> 3, c = idx & 7;
            cp16(As + row * ROWB + c * 16,
                 A + (size_t)(m0 + row) * K + k0 + c * 8);
        }
#pragma unroll
        for (int i = 0; i < 8; i++) {
            int idx = tid + i * 128;
            int row = idx >> 3, c = idx & 7;
            cp16(Bs + row * ROWB + c * 16,
                 B + (size_t)(n0 + row) * K + k0 + c * 8);
        }
        asm volatile("cp.async.commit_group;");
    };

    prefetch(0);

    float acc[4][8][4];
#pragma unroll
    for (int i = 0; i < 4; i++)
#pragma unroll
        for (int j = 0; j < 8; j++)
#pragma unroll
            for (int c = 0; c < 4; c++) acc[i][j][c] = 0.f;

    for (int it = 0; it < nIter; ++it) {
        if (it + 1 < nIter) {
            prefetch(it + 1);
            asm volatile("cp.async.wait_group 1;");
        } else {
            asm volatile("cp.async.wait_group 0;");
        }
        __syncthreads();

        const char* As = sm + (it & 1) * STG_BYTES;
        const char* Bs = As + TILE_BYTES;

#pragma unroll
        for (int ks = 0; ks < 4; ks++) {
            unsigned a[4][4], b[8][2];
#pragma unroll
            for (int i = 0; i < 4; i++) {
                const char* pa = As + (wm * 64 + i * 16 + grp) * ROWB + ks * 32 + thr * 4;
                a[i][0] = *(const unsigned*)pa;
                a[i][1] = *(const unsigned*)(pa + 8 * ROWB);
                a[i][2] = *(const unsigned*)(pa + 16);
                a[i][3] = *(const unsigned*)(pa + 8 * ROWB + 16);
            }
#pragma unroll
            for (int j = 0; j < 8; j++) {
                const char* pb = Bs + (wn * 64 + j * 8 + grp) * ROWB + ks * 32 + thr * 4;
                b[j][0] = *(const unsigned*)pb;
                b[j][1] = *(const unsigned*)(pb + 16);
            }
#pragma unroll
            for (int i = 0; i < 4; i++)
#pragma unroll
                for (int j = 0; j < 8; j++)
                    mma_f16(acc[i][j], a[i], b[j]);
        }
        __syncthreads();
    }

#pragma unroll
    for (int i = 0; i < 4; i++) {
        int row = m0 + wm * 64 + i * 16 + grp;
#pragma unroll
        for (int j = 0; j < 8; j++) {
            int col = n0 + wn * 64 + j * 8 + thr * 2;
            float v00 = acc[i][j][0], v01 = acc[i][j][1];
            float v10 = acc[i][j][2], v11 = acc[i][j][3];
            if (bias) {
                float2 bv = *(const float2*)(bias + col);
                v00 += bv.x; v01 += bv.y; v10 += bv.x; v11 += bv.y;
            }
            if (relu) {
                v00 = fmaxf(v00, 0.f); v01 = fmaxf(v01, 0.f);
                v10 = fmaxf(v10, 0.f); v11 = fmaxf(v11, 0.f);
            }
            if (halfC) {
                __half* C = (__half*)Cv;
                *(__half2*)(C + (size_t)row * ldc + col)       = __floats2half2_rn(v00, v01);
                *(__half2*)(C + (size_t)(row + 8) * ldc + col) = __floats2half2_rn(v10, v11);
            } else {
                float* C = (float*)Cv;
                *(float2*)(C + (size_t)row * ldc + col)       = make_float2(v00, v01);
                *(float2*)(C + (size_t)(row + 8) * ldc + col) = make_float2(v10, v11);
            }
        }
    }
}

__global__ void __launch_bounds__(128, 2)
gemm_h(const __half* __restrict__ A, const __half* __restrict__ B,
       const float* __restrict__ bias, void* __restrict__ C,
       int K, int ldc, int relu, int halfC)
{
    extern __shared__ char sm[];
    gemm_core_h(A, B, bias, C, K, ldc, relu, halfC,
                blockIdx.y * 128, blockIdx.x * 128, sm);
}

// fused QKV: blockIdx.z selects pair; outputs HALF q,k,v
__global__ void __launch_bounds__(128, 2)
gemm_qkv_h(const __half* __restrict__ xh,
           const __half* __restrict__ wqh, const __half* __restrict__ wkh,
           const __half* __restrict__ wvh,
           __half* __restrict__ q, __half* __restrict__ k, __half* __restrict__ v)
{
    extern __shared__ char sm[];
    const __half* B = (blockIdx.z == 0) ? wqh : (blockIdx.z == 1) ? wkh : wvh;
    __half*       C = (blockIdx.z == 0) ? q   : (blockIdx.z == 1) ? k   : v;
    gemm_core_h(xh, B, nullptr, C, DMODEL, DMODEL, 0, 1,
                blockIdx.y * 128, blockIdx.x * 128, sm);
}

// ---------------- causal flash attention, fp16 mma (m16n8k16) -------------------
// q,k,v half [B,S,H*64]; 64 queries/CTA, 4 warps; 64-key tiles.
// smem: Qs | Ks | Vs | Ps, each 64 rows x 144B (72 halves)
#define ARB 144
#define ATT_SMEM_BYTES (4 * 64 * ARB)   /* 36864 */

__global__ void __launch_bounds__(128)
attn_kernel(const __half* __restrict__ q, const __half* __restrict__ k,
            const __half* __restrict__ v, __half* __restrict__ out)
{
    extern __shared__ char asmem[];
    char* Qs = asmem;
    char* Ks = Qs + 64 * ARB;
    char* Vs = Ks + 64 * ARB;
    char* Ps = Vs + 64 * ARB;

    const int tid  = threadIdx.x;
    const int warp = tid >> 5, lane = tid & 31;
    const int grp = lane >> 2, thr = lane & 3;
    const int b = blockIdx.z, h = blockIdx.y;
    const int q0 = blockIdx.x * 64;
    const float SCALE = 0.125f;

    // ---- stage Q tile (half, cp.async) ----
#pragma unroll
    for (int i = 0; i < 4; i++) {
        int idx = tid + i * 128;
        int row = idx >> 3, c = idx & 7;
        cp16(Qs + row * ARB + c * 16,
             q + (size_t)(b * SEQ + q0 + row) * DMODEL + h * HS + c * 8);
    }
    asm volatile("cp.async.commit_group;");
    asm volatile("cp.async.wait_group 0;");
    __syncthreads();

    // ---- Q A-fragments (reused every key tile) ----
    const int rA = warp * 16 + grp;
    unsigned qf[4][4];
    {
        const char* pa = Qs + rA * ARB;
#pragma unroll
        for (int ks = 0; ks < 4; ks++) {
            qf[ks][0] = *(const unsigned*)(pa + ks * 32 + thr * 4);
            qf[ks][1] = *(const unsigned*)(pa + 8 * ARB + ks * 32 + thr * 4);
            qf[ks][2] = *(const unsigned*)(pa + ks * 32 + 16 + thr * 4);
            qf[ks][3] = *(const unsigned*)(pa + 8 * ARB + ks * 32 + 16 + thr * 4);
        }
    }

    float o[8][4];
#pragma unroll
    for (int j = 0; j < 8; j++)
#pragma unroll
        for (int c = 0; c < 4; c++) o[j][c] = 0.f;
    float m0 = -INFINITY, m1 = -INFINITY, l0 = 0.f, l1 = 0.f;
    const int r0g = q0 + rA, r1g = r0g + 8;
    const int nt = q0 / 64 + 1;

    for (int kt = 0; kt < nt; kt++) {
        const int kt0 = kt * 64;
        __syncthreads();    // prior-tile Ks/Vs/Ps reads done
        // K group, then V group (separate commits: S only needs K)
#pragma unroll
        for (int i = 0; i < 4; i++) {
            int idx = tid + i * 128;
            int row = idx >> 3, c = idx & 7;
            cp16(Ks + row * ARB + c * 16,
                 k + (size_t)(b * SEQ + kt0 + row) * DMODEL + h * HS + c * 8);
        }
        asm volatile("cp.async.commit_group;");
#pragma unroll
        for (int i = 0; i < 4; i++) {
            int idx = tid + i * 128;
            int row = idx >> 3, c = idx & 7;
            cp16(Vs + row * ARB + c * 16,
                 v + (size_t)(b * SEQ + kt0 + row) * DMODEL + h * HS + c * 8);
        }
        asm volatile("cp.async.commit_group;");
        asm volatile("cp.async.wait_group 1;");   // K ready
        __syncthreads();

        // ---- S = Q K^T ----
        float s[8][4];
#pragma unroll
        for (int j = 0; j < 8; j++) { s[j][0] = s[j][1] = s[j][2] = s[j][3] = 0.f; }
#pragma unroll
        for (int j = 0; j < 8; j++) {
            const char* pb = Ks + (j * 8 + grp) * ARB;
#pragma unroll
            for (int ks = 0; ks < 4; ks++) {
                unsigned bf[2];
                bf[0] = *(const unsigned*)(pb + ks * 32 + thr * 4);
                bf[1] = *(const unsigned*)(pb + ks * 32 + 16 + thr * 4);
                mma_f16(s[j], qf[ks], bf);
            }
        }

        // ---- scale + causal mask ----
        if (kt == nt - 1) {
#pragma unroll
            for (int j = 0; j < 8; j++) {
                int c0 = kt0 + j * 8 + 2 * thr;
                s[j][0] = (c0     <= r0g) ? s[j][0] * SCALE : -INFINITY;
                s[j][1] = (c0 + 1 <= r0g) ? s[j][1] * SCALE : -INFINITY;
                s[j][2] = (c0     <= r1g) ? s[j][2] * SCALE : -INFINITY;
                s[j][3] = (c0 + 1 <= r1g) ? s[j][3] * SCALE : -INFINITY;
            }
        } else {
#pragma unroll
            for (int j = 0; j < 8; j++) {
                s[j][0] *= SCALE; s[j][1] *= SCALE;
                s[j][2] *= SCALE; s[j][3] *= SCALE;
            }
        }

        // ---- online softmax ----
        float mx0 = -INFINITY, mx1 = -INFINITY;
#pragma unroll
        for (int j = 0; j < 8; j++) {
            mx0 = fmaxf(mx0, fmaxf(s[j][0], s[j][1]));
            mx1 = fmaxf(mx1, fmaxf(s[j][2], s[j][3]));
        }
        mx0 = fmaxf(mx0, __shfl_xor_sync(0xffffffffu, mx0, 1));
        mx0 = fmaxf(mx0, __shfl_xor_sync(0xffffffffu, mx0, 2));
        mx1 = fmaxf(mx1, __shfl_xor_sync(0xffffffffu, mx1, 1));
        mx1 = fmaxf(mx1, __shfl_xor_sync(0xffffffffu, mx1, 2));
        const float mn0 = fmaxf(m0, mx0), mn1 = fmaxf(m1, mx1);
        const float a0 = __expf(m0 - mn0), a1 = __expf(m1 - mn1);
        m0 = mn0; m1 = mn1;

        float ps0 = 0.f, ps1 = 0.f;
#pragma unroll
        for (int j = 0; j < 8; j++) {
            float p00 = __expf(s[j][0] - mn0);
            float p01 = __expf(s[j][1] - mn0);
            float p10 = __expf(s[j][2] - mn1);
            float p11 = __expf(s[j][3] - mn1);
            ps0 += p00 + p01; ps1 += p10 + p11;
            *(__half2*)(Ps + rA * ARB + j * 16 + thr * 4)       = __floats2half2_rn(p00, p01);
            *(__half2*)(Ps + (rA + 8) * ARB + j * 16 + thr * 4) = __floats2half2_rn(p10, p11);
        }
        ps0 += __shfl_xor_sync(0xffffffffu, ps0, 1);
        ps0 += __shfl_xor_sync(0xffffffffu, ps0, 2);
        ps1 += __shfl_xor_sync(0xffffffffu, ps1, 1);
        ps1 += __shfl_xor_sync(0xffffffffu, ps1, 2);
        l0 = l0 * a0 + ps0;
        l1 = l1 * a1 + ps1;

#pragma unroll
        for (int j = 0; j < 8; j++) {
            o[j][0] *= a0; o[j][1] *= a0;
            o[j][2] *= a1; o[j][3] *= a1;
        }
        asm volatile("cp.async.wait_group 0;");   // V ready
        __syncwarp();                              // P visible within warp

        // ---- O += P V : V^T fragments via ldmatrix.trans ----
#pragma unroll
        for (int ks = 0; ks < 4; ks++) {
            unsigned pa[4];
            const char* pp = Ps + rA * ARB + ks * 32 + thr * 4;
            pa[0] = *(const unsigned*)pp;
            pa[1] = *(const unsigned*)(pp + 8 * ARB);
            pa[2] = *(const unsigned*)(pp + 16);
            pa[3] = *(const unsigned*)(pp + 8 * ARB + 16);
#pragma unroll
            for (int jp = 0; jp < 4; jp++) {
                // lane l: tile t_=l>>3 (0..3), row r_=l&7
                // tile -> (j = 2jp + (t_>>1), key offset = (t_&1)*8)
                int t_ = lane >> 3, r_ = lane & 7;
                int jj = 2 * jp + (t_ >> 1), ko = (t_ & 1) * 8;
                uint32_t addr = s2u(Vs + (ks * 16 + ko + r_) * ARB + jj * 16);
                unsigned vb[4];
                ldmx4t(vb, addr);
                mma_f16(o[2 * jp],     pa, vb);      // uses vb[0],vb[1]
                mma_f16(o[2 * jp + 1], pa, vb + 2);  // uses vb[2],vb[3]
            }
        }
    }

    // ---- epilogue (half out) ----
    const float i0 = 1.f / l0, i1 = 1.f / l1;
    size_t base0 = (size_t)(b * SEQ + r0g) * DMODEL + h * HS;
    size_t base1 = (size_t)(b * SEQ + r1g) * DMODEL + h * HS;
#pragma unroll
    for (int j = 0; j < 8; j++) {
        int col = j * 8 + 2 * thr;
        *(__half2*)(out + base0 + col) = __floats2half2_rn(o[j][0] * i0, o[j][1] * i0);
        *(__half2*)(out + base1 + col) = __floats2half2_rn(o[j][2] * i1, o[j][3] * i1);
    }
}

// ---------------- fused residual + layernorm (one row per block) ----------------
__global__ void __launch_bounds__(256)
add_ln(const float* __restrict__ x, const float* __restrict__ y,
       const float* __restrict__ g, const float* __restrict__ be,
       float* __restrict__ out, __half* __restrict__ out_h)
{
    __shared__ float red[256];
    const int row = blockIdx.x, tid = threadIdx.x;
    const size_t base = (size_t)row * DMODEL;
    float4 xv = ((const float4*)(x + base))[tid];
    float4 yv = ((const float4*)(y + base))[tid];
    float v0 = xv.x + yv.x, v1 = xv.y + yv.y, v2 = xv.z + yv.z, v3 = xv.w + yv.w;

    red[tid] = v0 + v1 + v2 + v3;
    __syncthreads();
    for (int s = 128; s > 0; s >>= 1) {
        if (tid < s) red[tid] += red[tid + s];
        __syncthreads();
    }
    const float mu = red[0] * (1.f / DMODEL);
    __syncthreads();

    float d0 = v0 - mu, d1 = v1 - mu, d2 = v2 - mu, d3 = v3 - mu;
    red[tid] = d0 * d0 + d1 * d1 + d2 * d2 + d3 * d3;
    __syncthreads();
    for (int s = 128; s > 0; s >>= 1) {
        if (tid < s) red[tid] += red[tid + s];
        __syncthreads();
    }
    const float rstd = rsqrtf(red[0] * (1.f / DMODEL) + 1e-5f);

    float4 gv = ((const float4*)g)[tid];
    float4 bv = ((const float4*)be)[tid];
    float4 oo;
    oo.x = d0 * rstd * gv.x + bv.x;
    oo.y = d1 * rstd * gv.y + bv.y;
    oo.z = d2 * rstd * gv.z + bv.z;
    oo.w = d3 * rstd * gv.w + bv.w;
    ((float4*)(out + base))[tid] = oo;
    if (out_h) {
        *(__half2*)(out_h + base + tid * 4)     = __floats2half2_rn(oo.x, oo.y);
        *(__half2*)(out_h + base + tid * 4 + 2) = __floats2half2_rn(oo.z, oo.w);
    }
}

// ---------------- host driver ----------------
extern "C" void kernel_launch(void* const* d_in, const int* in_sizes, int n_in,
                              void* d_out, int out_size)
{
    const float* x      = (const float*)d_in[0];
    const float* wq     = (const float*)d_in[1];
    const float* wk     = (const float*)d_in[2];
    const float* wv     = (const float*)d_in[3];
    const float* w_proj = (const float*)d_in[4];
    const float* b_proj = (const float*)d_in[5];
    const float* w1     = (const float*)d_in[6];
    const float* b1     = (const float*)d_in[7];
    const float* w2     = (const float*)d_in[8];
    const float* b2     = (const float*)d_in[9];
    const float* g1     = (const float*)d_in[10];
    const float* be1    = (const float*)d_in[11];
    const float* g2     = (const float*)d_in[12];
    const float* be2    = (const float*)d_in[13];
    float* out = (float*)d_out;

    float *y, *x1, *y2;
    __half *q, *k, *v, *attn, *x1h, *hbuf, *xh;
    __half *wqh, *wkh, *wvh, *wph, *w1h, *w2h;
    cudaGetSymbolAddress((void**)&q,    g_q);
    cudaGetSymbolAddress((void**)&k,    g_k);
    cudaGetSymbolAddress((void**)&v,    g_v);
    cudaGetSymbolAddress((void**)&attn, g_attn);
    cudaGetSymbolAddress((void**)&y,    g_y);
    cudaGetSymbolAddress((void**)&x1,   g_x1);
    cudaGetSymbolAddress((void**)&x1h,  g_x1h);
    cudaGetSymbolAddress((void**)&hbuf, g_h);
    cudaGetSymbolAddress((void**)&y2,   g_y2);
    cudaGetSymbolAddress((void**)&xh,   g_xh);
    cudaGetSymbolAddress((void**)&wqh,  g_wqh);
    cudaGetSymbolAddress((void**)&wkh,  g_wkh);
    cudaGetSymbolAddress((void**)&wvh,  g_wvh);
    cudaGetSymbolAddress((void**)&wph,  g_wph);
    cudaGetSymbolAddress((void**)&w1h,  g_w1h);
    cudaGetSymbolAddress((void**)&w2h,  g_w2h);

    cudaFuncSetAttribute(attn_kernel,
                         cudaFuncAttributeMaxDynamicSharedMemorySize, ATT_SMEM_BYTES);
    cudaFuncSetAttribute(gemm_h,
                         cudaFuncAttributeMaxDynamicSharedMemorySize, GEMM_SMEM_BYTES);
    cudaFuncSetAttribute(gemm_qkv_h,
                         cudaFuncAttributeMaxDynamicSharedMemorySize, GEMM_SMEM_BYTES);

    dim3 tb(256);

    // ---- pre-pass: transpose+convert weights to half [N][K]; convert x ----
    transpose_h<<<dim3(HS/32, DMODEL/32, NH), tb>>>(wq, wqh, DMODEL, HS);
    transpose_h<<<dim3(HS/32, DMODEL/32, NH), tb>>>(wk, wkh, DMODEL, HS);
    transpose_h<<<dim3(HS/32, DMODEL/32, NH), tb>>>(wv, wvh, DMODEL, HS);
    transpose_h<<<dim3(DMODEL/32, DMODEL/32, 1), tb>>>(w_proj, wph, DMODEL, DMODEL);
    transpose_h<<<dim3(FF/32, DMODEL/32, 1), tb>>>(w1, w1h, DMODEL, FF);
    transpose_h<<<dim3(DMODEL/32, FF/32, 1), tb>>>(w2, w2h, FF, DMODEL);
    round_h<<<592, 256>>>(x, xh, MTOT*DMODEL/4);

    dim3 gb(128);

    // fused QKV -> HALF q,k,v in [B,S,H*64]
    dim3 gqkv(DMODEL / 128, MTOT / 128, 3);      // (8, 32, 3)
    gemm_qkv_h<<<gqkv, gb, GEMM_SMEM_BYTES>>>(xh, wqh, wkh, wvh, q, k, v);

    // causal attention (fp16 mma) -> half attn
    dim3 ga(SEQ / 64, NH, BATCH);                // (32, 16, 2)
    attn_kernel<<<ga, dim3(128), ATT_SMEM_BYTES>>>(q, k, v, attn);

    // output projection (fp32 C)
    dim3 gq(DMODEL / 128, MTOT / 128);           // (8, 32)
    gemm_h<<<gq, gb, GEMM_SMEM_BYTES>>>(attn, wph, b_proj, y, DMODEL, DMODEL, 0, 0);

    // x1 = LN(x + y); also half twin
    add_ln<<<MTOT, tb>>>(x, y, g1, be1, x1, x1h);

    // MLP
    dim3 gm1(FF / 128, MTOT / 128);              // (32, 32)
    gemm_h<<<gm1, gb, GEMM_SMEM_BYTES>>>(x1h, w1h, b1, hbuf, DMODEL, FF, 1, 1);
    dim3 gm2(DMODEL / 128, MTOT / 128);          // (8, 32)
    gemm_h<<<gm2, gb, GEMM_SMEM_BYTES>>>(hbuf, w2h, b2, y2, FF, DMODEL, 0, 0);

    // out = LN(x1 + y2)
    add_ln<<<MTOT, tb>>>(x1, y2, g2, be2, out, nullptr);
}